// round 11
// baseline (speedup 1.0000x reference)
#include <cuda_runtime.h>
#include <cuda_bf16.h>
#include <cstdint>

#define GG  49
#define HP  51
#define HID 150
#define BB  128
#define CC  2
#define AA  8
#define KK  30
#define CI_BLK 10
#define NPIX (GG * GG)          // 2401

typedef unsigned long long u64;

// ---------------- f32x2 helpers (trans kernel) ----------------
__device__ __forceinline__ u64 pack2(float x, float y) {
    u64 r; asm("mov.b64 %0, {%1,%2};" : "=l"(r) : "f"(x), "f"(y)); return r;
}
__device__ __forceinline__ void ffma2(u64& acc, u64 a, u64 b) {
    asm("fma.rn.f32x2 %0, %1, %2, %0;" : "+l"(acc) : "l"(a), "l"(b));
}
__device__ __forceinline__ float2 unpack2(u64 v) {
    float2 f; asm("mov.b64 {%0,%1}, %2;" : "=f"(f.x), "=f"(f.y) : "l"(v)); return f;
}

// ---------------- mma.sync bf16 (compute_80 baseline -> works under compute_103) ----------------
__device__ __forceinline__ void mma16816(float* d,
                                         uint32_t a0, uint32_t a1, uint32_t a2, uint32_t a3,
                                         uint32_t b0, uint32_t b1) {
    asm volatile(
        "mma.sync.aligned.m16n8k16.row.col.f32.bf16.bf16.f32 "
        "{%0,%1,%2,%3}, {%4,%5,%6,%7}, {%8,%9}, {%0,%1,%2,%3};"
        : "+f"(d[0]), "+f"(d[1]), "+f"(d[2]), "+f"(d[3])
        : "r"(a0), "r"(a1), "r"(a2), "r"(a3), "r"(b0), "r"(b1));
}

// ---------------- scratch ----------------
__device__ float g_h1[BB * HID * NPIX];
__device__ float g_h2[BB * HID * NPIX];
__device__ float g_sT[BB * AA * 9 * HP * HP];
__device__ float g_reward[BB * HP * HP];
__device__ float g_qc[BB * AA * NPIX];
// pre-split conv2 weights, layout [t][ci(160)][n(160)] bf16 hi/lo
__device__ __nv_bfloat16 g_wh[9 * 160 * 160];
__device__ __nv_bfloat16 g_wl[9 * 160 * 160];

// ---------------- weight split precompute ----------------
__global__ __launch_bounds__(256) void wsplit_kernel(const float* __restrict__ w) {
    int idx = blockIdx.x * 256 + threadIdx.x;
    if (idx >= 9 * 160 * 160) return;
    int n = idx % 160;
    int rest = idx / 160;
    int ci = rest % 160;
    int t = rest / 160;
    float v = 0.f;
    if (n < HID && ci < HID) v = w[n * (HID * 9) + ci * 9 + t];
    __nv_bfloat16 h = __float2bfloat16(v);
    g_wh[idx] = h;
    g_wl[idx] = __float2bfloat16(v - __bfloat162float(h));
}

// ---------------- conv1 (unchanged) ----------------
__global__ __launch_bounds__(256) void conv1_kernel(const float* __restrict__ gin,
                                                    const float* __restrict__ w,
                                                    const float* __restrict__ bias) {
    int b = blockIdx.y;
    int r0 = blockIdx.x * 7;
    __shared__ float tile[CC * 9 * 51];
    __shared__ float ws[HID * 18];
    __shared__ float bs[HID];
    int tid = threadIdx.x;

    for (int i = tid; i < CC * 9 * 51; i += 256) {
        int ci = i / (9 * 51);
        int rr = (i / 51) % 9;
        int cc = i % 51;
        int gr = r0 + rr - 1, gc = cc - 1;
        float v = 0.f;
        if (gr >= 0 && gr < GG && gc >= 0 && gc < GG)
            v = gin[(b * CC + ci) * NPIX + gr * GG + gc];
        tile[i] = v;
    }
    for (int i = tid; i < HID * 18; i += 256) ws[i] = w[i];
    for (int i = tid; i < HID; i += 256) bs[i] = bias[i];
    __syncthreads();

    for (int pp = tid; pp < 7 * GG; pp += 256) {
        int lr = pp / GG, lc = pp % GG;
        int gr = r0 + lr;
        if (gr >= GG) continue;
        float patch[18];
#pragma unroll
        for (int ci = 0; ci < CC; ci++)
#pragma unroll
            for (int k = 0; k < 9; k++)
                patch[ci * 9 + k] = tile[ci * 9 * 51 + (lr + k / 3) * 51 + (lc + k % 3)];
        for (int co = 0; co < HID; co++) {
            float a = bs[co];
            const float2* wp = (const float2*)&ws[co * 18];
#pragma unroll
            for (int j = 0; j < 9; j++) {
                float2 w2 = wp[j];
                a = fmaf(patch[2 * j], w2.x, a);
                a = fmaf(patch[2 * j + 1], w2.y, a);
            }
            g_h1[(b * HID + co) * NPIX + gr * GG + lc] = fmaxf(a, 0.f);
        }
    }
}

// ---------------- conv2 via mma.sync bf16 (3-term split) ----------------
// CTA per (128-pixel tile, batch). D[128, 160] over 45 stages (9 taps x 5 ci-chunks of 32).
// 8 warps = 4(M) x 2(N); warp tile 32 x 80 = 2 x 10 m16n8k16 accum tiles.
// smem: AH/AL [128 x 32] bf16 pitch 36, BH/BL [160 x 32] bf16 pitch 36. 41472 B total.
#define C2_SMEM 41472

__global__ __launch_bounds__(256) void conv2_mma_kernel(const float* __restrict__ bias) {
    extern __shared__ char smc[];
    char* AHp = smc;
    char* ALp = smc + 9216;
    char* BHp = smc + 18432;
    char* BLp = smc + 29952;
    float* DT = (float*)smc;

    int tid = threadIdx.x;
    int lane = tid & 31, wid = tid >> 5;
    int b = blockIdx.y;
    int p0 = blockIdx.x * 128;
    int m0 = (wid & 3) * 32;
    int wn = wid >> 2;
    int n0 = wn * 80;
    int row = lane >> 2;
    int kq = (lane & 3) * 2;

    const float* __restrict__ h1b = &g_h1[(size_t)b * HID * NPIX];

    float acc[2][10][4];
#pragma unroll
    for (int mi = 0; mi < 2; mi++)
#pragma unroll
        for (int ni = 0; ni < 10; ni++)
#pragma unroll
            for (int j = 0; j < 4; j++) acc[mi][ni][j] = 0.f;

    for (int t = 0; t < 9; t++) {
        int dr = t / 3 - 1, dc = t % 3 - 1;
        for (int cb = 0; cb < 160; cb += 32) {
            __syncthreads();
            // ---- build A [128 x 32] hi/lo ----
            for (int i = tid; i < 4096; i += 256) {
                int m = i & 127, k = i >> 7;
                int p = p0 + m; if (p >= NPIX) p = NPIX - 1;
                int r = p / GG, c = p % GG;
                int rr = r + dr, cc = c + dc;
                int ci = cb + k;
                float v = 0.f;
                if (rr >= 0 && rr < GG && cc >= 0 && cc < GG && ci < HID)
                    v = h1b[ci * NPIX + rr * GG + cc];
                __nv_bfloat16 h = __float2bfloat16(v);
                __nv_bfloat16 l = __float2bfloat16(v - __bfloat162float(h));
                ((__nv_bfloat16*)AHp)[m * 36 + k] = h;
                ((__nv_bfloat16*)ALp)[m * 36 + k] = l;
            }
            // ---- build B [160 x 32] hi/lo from pre-split weights ----
            for (int i = tid; i < 5120; i += 256) {
                int n = i % 160, k = i / 160;
                int src = (t * 160 + cb + k) * 160 + n;
                ((__nv_bfloat16*)BHp)[n * 36 + k] = g_wh[src];
                ((__nv_bfloat16*)BLp)[n * 36 + k] = g_wl[src];
            }
            __syncthreads();
            // ---- MMA ----
#pragma unroll
            for (int k16 = 0; k16 < 32; k16 += 16) {
                int kk = k16 + kq;
                uint32_t ah[2][4], al[2][4];
#pragma unroll
                for (int mi = 0; mi < 2; mi++) {
                    int mr = m0 + mi * 16 + row;
                    ah[mi][0] = *(const uint32_t*)(AHp + mr * 72 + kk * 2);
                    ah[mi][1] = *(const uint32_t*)(AHp + (mr + 8) * 72 + kk * 2);
                    ah[mi][2] = *(const uint32_t*)(AHp + mr * 72 + (kk + 8) * 2);
                    ah[mi][3] = *(const uint32_t*)(AHp + (mr + 8) * 72 + (kk + 8) * 2);
                    al[mi][0] = *(const uint32_t*)(ALp + mr * 72 + kk * 2);
                    al[mi][1] = *(const uint32_t*)(ALp + (mr + 8) * 72 + kk * 2);
                    al[mi][2] = *(const uint32_t*)(ALp + mr * 72 + (kk + 8) * 2);
                    al[mi][3] = *(const uint32_t*)(ALp + (mr + 8) * 72 + (kk + 8) * 2);
                }
#pragma unroll
                for (int ni = 0; ni < 10; ni++) {
                    int nr = n0 + ni * 8 + row;
                    uint32_t bh0 = *(const uint32_t*)(BHp + nr * 72 + kk * 2);
                    uint32_t bh1 = *(const uint32_t*)(BHp + nr * 72 + (kk + 8) * 2);
                    uint32_t bl0 = *(const uint32_t*)(BLp + nr * 72 + kk * 2);
                    uint32_t bl1 = *(const uint32_t*)(BLp + nr * 72 + (kk + 8) * 2);
#pragma unroll
                    for (int mi = 0; mi < 2; mi++) {
                        mma16816(acc[mi][ni], ah[mi][0], ah[mi][1], ah[mi][2], ah[mi][3], bh0, bh1);
                        mma16816(acc[mi][ni], ah[mi][0], ah[mi][1], ah[mi][2], ah[mi][3], bl0, bl1);
                        mma16816(acc[mi][ni], al[mi][0], al[mi][1], al[mi][2], al[mi][3], bh0, bh1);
                    }
                }
            }
        }
    }

    // ---- epilogue: stage through smem, coalesced [co][pixel] stores ----
#pragma unroll 1
    for (int h = 0; h < 2; h++) {
        __syncthreads();
        if (wn == h) {
#pragma unroll
            for (int mi = 0; mi < 2; mi++)
#pragma unroll
                for (int ni = 0; ni < 10; ni++) {
                    int mb = m0 + mi * 16 + row;
                    int nb = ni * 8 + (lane & 3) * 2;
                    DT[mb * 80 + nb]           = acc[mi][ni][0];
                    DT[mb * 80 + nb + 1]       = acc[mi][ni][1];
                    DT[(mb + 8) * 80 + nb]     = acc[mi][ni][2];
                    DT[(mb + 8) * 80 + nb + 1] = acc[mi][ni][3];
                }
        }
        __syncthreads();
        for (int idx = tid; idx < 10240; idx += 256) {
            int m = idx & 127, nl = idx >> 7;
            int co = h * 80 + nl;
            int p = p0 + m;
            if (co < HID && p < NPIX) {
                float v = fmaxf(DT[m * 80 + nl] + bias[co], 0.f);
                g_h2[((size_t)b * HID + co) * NPIX + p] = v;
            }
        }
    }
}

// ---------------- trans (72ch) + reward conv, scalar f32x2 (unchanged) ----------------
__global__ __launch_bounds__(512) void trans_kernel(const float* __restrict__ tw,
                                                    const float* __restrict__ rw) {
    int b = blockIdx.y;
    int r0 = blockIdx.x * 3;
    __shared__ __align__(16) float tile[CI_BLK * 5 * 53];
    __shared__ __align__(16) float ws[CI_BLK * 9 * 90];
    int tid = threadIdx.x;
    int col = tid % HP;
    int g = tid / HP;
    bool act = tid < 9 * HP;

    u64   acc[3][4];
    float acc8[3];
#pragma unroll
    for (int r = 0; r < 3; r++) {
#pragma unroll
        for (int j = 0; j < 4; j++) acc[r][j] = 0ULL;
        acc8[r] = 0.f;
    }

    for (int cib = 0; cib < HID; cib += CI_BLK) {
        for (int i = tid; i < CI_BLK * 5 * 53; i += 512) {
            int ci = i / 265;
            int rem = i % 265;
            int rr = rem / 53, cc = rem % 53;
            int gr = r0 + rr - 2, gc = cc - 2;
            float v = 0.f;
            if (gr >= 0 && gr < GG && gc >= 0 && gc < GG)
                v = g_h2[(b * HID + cib + ci) * NPIX + gr * GG + gc];
            tile[i] = v;
        }
        for (int i = tid; i < CI_BLK * 9 * 90; i += 512) {
            int ci = i / 810;
            int rem = i % 810;
            int k = rem / 90, chp = rem % 90;
            int gg2 = chp / 10, j = chp % 10;
            float v = 0.f;
            if (j < 9) {
                int ch = gg2 * 9 + j;
                if (ch < 72) v = tw[ch * (HID * 9) + (cib + ci) * 9 + k];
                else if (ch == 72) v = rw[(cib + ci) * 9 + k];
            }
            ws[(ci * 9 + k) * 90 + chp] = v;
        }
        __syncthreads();
        if (act) {
            for (int ci = 0; ci < CI_BLK; ci++) {
                const float* tb = &tile[ci * 265 + col];
#pragma unroll
                for (int dc = 0; dc < 3; dc++) {
                    u64 pp[5];
                    float pf[5];
#pragma unroll
                    for (int r = 0; r < 5; r++) {
                        pf[r] = tb[r * 53 + dc];
                        pp[r] = pack2(pf[r], pf[r]);
                    }
#pragma unroll
                    for (int dr = 0; dr < 3; dr++) {
                        const float* wvf = &ws[(ci * 9 + dr * 3 + dc) * 90 + g * 10];
                        const u64* wp = (const u64*)wvf;
                        u64 w0 = wp[0], w1 = wp[1], w2 = wp[2], w3 = wp[3];
                        float w8 = wvf[8];
#pragma unroll
                        for (int rr = 0; rr < 3; rr++) {
                            u64 pv = pp[rr + dr];
                            ffma2(acc[rr][0], pv, w0);
                            ffma2(acc[rr][1], pv, w1);
                            ffma2(acc[rr][2], pv, w2);
                            ffma2(acc[rr][3], pv, w3);
                            acc8[rr] = fmaf(pf[rr + dr], w8, acc8[rr]);
                        }
                    }
                }
            }
        }
        __syncthreads();
    }
    if (act) {
#pragma unroll
        for (int rr = 0; rr < 3; rr++) {
            int p = (r0 + rr) * HP + col;
            float av[9];
#pragma unroll
            for (int j = 0; j < 4; j++) {
                float2 v = unpack2(acc[rr][j]);
                av[2 * j] = v.x;
                av[2 * j + 1] = v.y;
            }
            av[8] = acc8[rr];
            if (g < 8) {
                float m = av[0];
#pragma unroll
                for (int j = 1; j < 9; j++) m = fmaxf(m, av[j]);
                float e[9];
                float s = 0.f;
#pragma unroll
                for (int j = 0; j < 9; j++) { e[j] = expf(av[j] - m); s += e[j]; }
                float inv = 1.0f / s;
#pragma unroll
                for (int j = 0; j < 9; j++)
                    g_sT[((b * AA + g) * 9 + j) * (HP * HP) + p] = e[j] * inv;
            } else {
                g_reward[b * HP * HP + p] = av[0];
            }
        }
    }
}

// ---------------- VI loop (unchanged) ----------------
__global__ __launch_bounds__(1024) void vi_kernel() {
    int b = blockIdx.x;
    __shared__ float vpad[53 * 53];
    __shared__ float rsh[HP * HP];
    int tid = threadIdx.x;
    for (int i = tid; i < 53 * 53; i += 1024) vpad[i] = 0.f;
    for (int i = tid; i < HP * HP; i += 1024) rsh[i] = g_reward[b * HP * HP + i];
    const float* __restrict__ sb = &g_sT[(size_t)b * AA * 9 * HP * HP];

    for (int it = 0; it < KK; it++) {
        __syncthreads();
        float vnew[3];
#pragma unroll
        for (int j = 0; j < 3; j++) {
            int p = tid + j * 1024;
            if (p < HP * HP) {
                int r = p / HP, c = p % HP;
                float patch[9];
#pragma unroll
                for (int k = 0; k < 9; k++)
                    patch[k] = vpad[(r + k / 3) * 53 + (c + k % 3)];
                float rwv = rsh[p];
                float vm = -3.4e38f;
#pragma unroll
                for (int a = 0; a < AA; a++) {
                    float q = rwv;
#pragma unroll
                    for (int k = 0; k < 9; k++)
                        q = fmaf(sb[(a * 9 + k) * (HP * HP) + p], patch[k], q);
                    vm = fmaxf(vm, q);
                    if (it == KK - 1 && r < GG && c < GG)
                        g_qc[((b * AA + a) * GG + r) * GG + c] = q;
                }
                vnew[j] = vm;
            }
        }
        __syncthreads();
#pragma unroll
        for (int j = 0; j < 3; j++) {
            int p = tid + j * 1024;
            if (p < HP * HP) {
                int r = p / HP, c = p % HP;
                vpad[(r + 1) * 53 + (c + 1)] = vnew[j];
            }
        }
    }
}

// ---------------- head (unchanged) ----------------
__global__ __launch_bounds__(256) void head_kernel(const float* __restrict__ w1,
                                                   const float* __restrict__ b1g,
                                                   const float* __restrict__ w2,
                                                   const float* __restrict__ b2g,
                                                   float* __restrict__ out) {
    int b = blockIdx.y;
    int p = blockIdx.x * 256 + threadIdx.x;
    __shared__ float w1s[HID * AA];
    __shared__ float b1s[HID];
    __shared__ float w2s[HID * AA];
    __shared__ float b2s[AA];
    int tid = threadIdx.x;
    for (int i = tid; i < HID * AA; i += 256) w1s[i] = w1[i];
    for (int i = tid; i < HID; i += 256) b1s[i] = b1g[i];
    for (int i = tid; i < HID * AA; i += 256) {
        int a = i / HID, c = i % HID;
        w2s[c * AA + a] = w2[i];
    }
    for (int i = tid; i < AA; i += 256) b2s[i] = b2g[i];
    __syncthreads();
    if (p >= NPIX) return;

    float qv[AA];
#pragma unroll
    for (int a = 0; a < AA; a++) qv[a] = g_qc[(b * AA + a) * NPIX + p];
    float o[AA];
#pragma unroll
    for (int a = 0; a < AA; a++) o[a] = b2s[a];

    for (int c = 0; c < HID; c++) {
        const float2* wp1 = (const float2*)&w1s[c * 8];
        float m = b1s[c];
#pragma unroll
        for (int j = 0; j < 4; j++) {
            float2 ww = wp1[j];
            m = fmaf(qv[2 * j], ww.x, m);
            m = fmaf(qv[2 * j + 1], ww.y, m);
        }
        m = fmaxf(m, 0.f);
        const float2* wp2 = (const float2*)&w2s[c * 8];
#pragma unroll
        for (int j = 0; j < 4; j++) {
            float2 ww = wp2[j];
            o[2 * j]     = fmaf(m, ww.x, o[2 * j]);
            o[2 * j + 1] = fmaf(m, ww.y, o[2 * j + 1]);
        }
    }
#pragma unroll
    for (int a = 0; a < AA; a++)
        out[(b * AA + a) * NPIX + p] = o[a];
}

// ---------------- launch ----------------
extern "C" void kernel_launch(void* const* d_in, const int* in_sizes, int n_in,
                              void* d_out, int out_size) {
    const float* grid_in = (const float*)d_in[0];
    const float* h1_w = (const float*)d_in[3];
    const float* h1_b = (const float*)d_in[4];
    const float* h2_w = (const float*)d_in[5];
    const float* h2_b = (const float*)d_in[6];
    const float* r_w  = (const float*)d_in[7];
    const float* t_w  = (const float*)d_in[8];
    const float* a1_w = (const float*)d_in[9];
    const float* a1_b = (const float*)d_in[10];
    const float* a2_w = (const float*)d_in[11];
    const float* a2_b = (const float*)d_in[12];

    cudaFuncSetAttribute(conv2_mma_kernel, cudaFuncAttributeMaxDynamicSharedMemorySize, C2_SMEM);

    wsplit_kernel<<<(9 * 160 * 160 + 255) / 256, 256>>>(h2_w);
    conv1_kernel<<<dim3(7, BB), 256>>>(grid_in, h1_w, h1_b);
    conv2_mma_kernel<<<dim3((NPIX + 127) / 128, BB), 256, C2_SMEM>>>(h2_b);
    trans_kernel<<<dim3(17, BB), 512>>>(t_w, r_w);
    vi_kernel<<<BB, 1024>>>();
    head_kernel<<<dim3(10, BB), 256>>>(a1_w, a1_b, a2_w, a2_b, (float*)d_out);
}

// round 13
// speedup vs baseline: 1.3092x; 1.3092x over previous
#include <cuda_runtime.h>
#include <cuda_bf16.h>
#include <cstdint>

#define GG  49
#define HP  51
#define HID 150
#define BB  128
#define CC  2
#define AA  8
#define KK  30
#define CI_BLK 10
#define NPIX (GG * GG)          // 2401

typedef unsigned long long u64;

// ---------------- f32x2 helpers (trans kernel) ----------------
__device__ __forceinline__ u64 pack2(float x, float y) {
    u64 r; asm("mov.b64 %0, {%1,%2};" : "=l"(r) : "f"(x), "f"(y)); return r;
}
__device__ __forceinline__ void ffma2(u64& acc, u64 a, u64 b) {
    asm("fma.rn.f32x2 %0, %1, %2, %0;" : "+l"(acc) : "l"(a), "l"(b));
}
__device__ __forceinline__ float2 unpack2(u64 v) {
    float2 f; asm("mov.b64 {%0,%1}, %2;" : "=f"(f.x), "=f"(f.y) : "l"(v)); return f;
}

// ---------------- mma / ldmatrix / cp.async (compute_80 baseline) ----------------
__device__ __forceinline__ void mma16816(float* d,
                                         uint32_t a0, uint32_t a1, uint32_t a2, uint32_t a3,
                                         uint32_t b0, uint32_t b1) {
    asm volatile(
        "mma.sync.aligned.m16n8k16.row.col.f32.bf16.bf16.f32 "
        "{%0,%1,%2,%3}, {%4,%5,%6,%7}, {%8,%9}, {%0,%1,%2,%3};"
        : "+f"(d[0]), "+f"(d[1]), "+f"(d[2]), "+f"(d[3])
        : "r"(a0), "r"(a1), "r"(a2), "r"(a3), "r"(b0), "r"(b1));
}
__device__ __forceinline__ void ldm4(uint32_t& r0, uint32_t& r1, uint32_t& r2, uint32_t& r3,
                                     uint32_t addr) {
    asm volatile("ldmatrix.sync.aligned.m8n8.x4.shared.b16 {%0,%1,%2,%3}, [%4];"
                 : "=r"(r0), "=r"(r1), "=r"(r2), "=r"(r3) : "r"(addr));
}
__device__ __forceinline__ void cp16(uint32_t dst, const void* src, int sz) {
    asm volatile("cp.async.cg.shared.global [%0], [%1], 16, %2;"
                 :: "r"(dst), "l"(src), "r"(sz));
}
__device__ __forceinline__ uint32_t smem_u32(const void* p) {
    uint32_t a;
    asm("{ .reg .u64 t; cvta.to.shared.u64 t, %1; cvt.u32.u64 %0, t; }" : "=r"(a) : "l"(p));
    return a;
}

// ---------------- scratch ----------------
__device__ float g_h1[BB * HID * NPIX];
__device__ float g_h2[BB * HID * NPIX];
__device__ float g_sT[BB * AA * 9 * HP * HP];
__device__ float g_reward[BB * HP * HP];
__device__ float g_qc[BB * AA * NPIX];
// channel-last bf16 hi/lo planes of h1: [b][pix][160]
__device__ __nv_bfloat16 g_h1h[(size_t)BB * NPIX * 160];
__device__ __nv_bfloat16 g_h1l[(size_t)BB * NPIX * 160];
// pre-split conv2 weights, layout [t][n(160)][ci(160)]
__device__ __nv_bfloat16 g_wh[9 * 160 * 160];
__device__ __nv_bfloat16 g_wl[9 * 160 * 160];

// ---------------- weight split ([t][n][ci], zero-padded) ----------------
__global__ __launch_bounds__(256) void wsplit_kernel(const float* __restrict__ w) {
    int idx = blockIdx.x * 256 + threadIdx.x;
    if (idx >= 9 * 160 * 160) return;
    int ci = idx % 160;
    int rest = idx / 160;
    int n = rest % 160;
    int t = rest / 160;
    float v = 0.f;
    if (n < HID && ci < HID) v = w[n * (HID * 9) + ci * 9 + t];
    __nv_bfloat16 h = __float2bfloat16(v);
    g_wh[idx] = h;
    g_wl[idx] = __float2bfloat16(v - __bfloat162float(h));
}

// ---------------- h1 transpose + split: [b][ci][pix] f32 -> [b][pix][160] bf16 hi/lo ----------------
__global__ __launch_bounds__(256) void h1split_kernel() {
    int b = blockIdx.z;
    int p0 = blockIdx.x * 64;
    __shared__ float ts[160][65];
    int tid = threadIdx.x;
    for (int i = tid; i < 160 * 64; i += 256) {
        int ci = i >> 6, pl = i & 63;
        float v = 0.f;
        int p = p0 + pl;
        if (ci < HID && p < NPIX) v = g_h1[((size_t)b * HID + ci) * NPIX + p];
        ts[ci][pl] = v;
    }
    __syncthreads();
    for (int i = tid; i < 64 * 160; i += 256) {
        int pl = i / 160, ci = i % 160;
        int p = p0 + pl;
        if (p < NPIX) {
            float v = ts[ci][pl];
            __nv_bfloat16 h = __float2bfloat16(v);
            size_t o = ((size_t)b * NPIX + p) * 160 + ci;
            g_h1h[o] = h;
            g_h1l[o] = __float2bfloat16(v - __bfloat162float(h));
        }
    }
}

// ---------------- conv1 (unchanged) ----------------
__global__ __launch_bounds__(256) void conv1_kernel(const float* __restrict__ gin,
                                                    const float* __restrict__ w,
                                                    const float* __restrict__ bias) {
    int b = blockIdx.y;
    int r0 = blockIdx.x * 7;
    __shared__ float tile[CC * 9 * 51];
    __shared__ float ws[HID * 18];
    __shared__ float bs[HID];
    int tid = threadIdx.x;

    for (int i = tid; i < CC * 9 * 51; i += 256) {
        int ci = i / (9 * 51);
        int rr = (i / 51) % 9;
        int cc = i % 51;
        int gr = r0 + rr - 1, gc = cc - 1;
        float v = 0.f;
        if (gr >= 0 && gr < GG && gc >= 0 && gc < GG)
            v = gin[(b * CC + ci) * NPIX + gr * GG + gc];
        tile[i] = v;
    }
    for (int i = tid; i < HID * 18; i += 256) ws[i] = w[i];
    for (int i = tid; i < HID; i += 256) bs[i] = bias[i];
    __syncthreads();

    for (int pp = tid; pp < 7 * GG; pp += 256) {
        int lr = pp / GG, lc = pp % GG;
        int gr = r0 + lr;
        if (gr >= GG) continue;
        float patch[18];
#pragma unroll
        for (int ci = 0; ci < CC; ci++)
#pragma unroll
            for (int k = 0; k < 9; k++)
                patch[ci * 9 + k] = tile[ci * 9 * 51 + (lr + k / 3) * 51 + (lc + k % 3)];
        for (int co = 0; co < HID; co++) {
            float a = bs[co];
            const float2* wp = (const float2*)&ws[co * 18];
#pragma unroll
            for (int j = 0; j < 9; j++) {
                float2 w2 = wp[j];
                a = fmaf(patch[2 * j], w2.x, a);
                a = fmaf(patch[2 * j + 1], w2.y, a);
            }
            g_h1[(b * HID + co) * NPIX + gr * GG + lc] = fmaxf(a, 0.f);
        }
    }
}

// ---------------- conv2: mma.sync bf16 3-term, cp.async double-buffer, ldmatrix ----------------
// CTA per (128-pixel tile, batch). D[128, 160], 45 stages (9 taps x 5 ci-chunks of 32).
// smem: A[2buf][2pl][128 rows x 64B] = 32KB, B[2buf][2pl][160 rows x 64B] = 40KB. 72KB.
// Swizzle: 16B-chunk index ^= (row>>1)&3  (conflict-free for ldmatrix 8-row phases).
#define C2_SMEM 73728

__global__ void __launch_bounds__(256, 2) conv2_mma_kernel(const float* __restrict__ bias) {
    extern __shared__ char smc[];
    uint32_t sb = smem_u32(smc);
    int tid = threadIdx.x;
    int lane = tid & 31, wid = tid >> 5;
    int b = blockIdx.y;
    int p0 = blockIdx.x * 128;
    int m0 = (wid & 3) * 32;
    int wn = wid >> 2;
    int n0 = wn * 80;

    // A-load mapping: thread -> (row m, plane)
    int mrow = tid & 127;
    int aplane = tid >> 7;
    int pa = p0 + mrow; if (pa > NPIX - 1) pa = NPIX - 1;
    int par = pa / GG, pac = pa % GG;
    const __nv_bfloat16* abase = (aplane ? g_h1l : g_h1h) + (size_t)b * NPIX * 160;
    uint32_t adst0 = sb + aplane * 8192 + mrow * 64;
    int aswz = (mrow >> 1) & 3;

    // fragment address precompute
    int mat = lane >> 3, wl = lane & 7;
    int rowA0 = m0 + ((mat & 1) << 3) + wl;
    int rowA1 = rowA0 + 16;
    int sA0 = (rowA0 >> 1) & 3;
    int sA1 = (rowA1 >> 1) & 3;
    int kmatA = mat >> 1;
    int rowBb = n0 + (((mat >> 1) & 1) << 3) + wl;
    int kmatB = mat & 1;

    float acc[2][10][4];
#pragma unroll
    for (int mi = 0; mi < 2; mi++)
#pragma unroll
        for (int ni = 0; ni < 10; ni++)
#pragma unroll
            for (int j = 0; j < 4; j++) acc[mi][ni][j] = 0.f;

    auto load_stage = [&](int s, int bs) {
        int t = s / 5;
        int cb = (s - t * 5) * 32;
        int dr = t / 3 - 1, dc = t - (t / 3) * 3 - 1;
        int rr = par + dr, cc = pac + dc;
        bool val = ((unsigned)rr < GG) && ((unsigned)cc < GG);
        const __nv_bfloat16* src = abase + (size_t)(val ? (rr * GG + cc) : 0) * 160 + cb;
        int sz = val ? 16 : 0;
        uint32_t d = adst0 + bs * 16384;
#pragma unroll
        for (int j = 0; j < 4; j++)
            cp16(d + (((unsigned)(j ^ aswz)) << 4), (const char*)src + j * 16, sz);
        for (int rp = tid; rp < 320; rp += 256) {
            int bp = rp >= 160 ? 1 : 0;
            int n = rp - bp * 160;
            const __nv_bfloat16* wsrc = (bp ? g_wl : g_wh) + (size_t)(t * 160 + n) * 160 + cb;
            uint32_t bd = sb + 32768 + bs * 20480 + bp * 10240 + n * 64;
            int bsw = (n >> 1) & 3;
#pragma unroll
            for (int j = 0; j < 4; j++)
                cp16(bd + (((unsigned)(j ^ bsw)) << 4), (const char*)wsrc + j * 16, 16);
        }
        asm volatile("cp.async.commit_group;" ::: "memory");
    };

    load_stage(0, 0);
    for (int s = 0; s < 45; s++) {
        int bs = s & 1;
        if (s + 1 < 45) {
            load_stage(s + 1, (s + 1) & 1);
            asm volatile("cp.async.wait_group 1;" ::: "memory");
        } else {
            asm volatile("cp.async.wait_group 0;" ::: "memory");
        }
        __syncthreads();
        uint32_t Ah = sb + bs * 16384;
        uint32_t Al = Ah + 8192;
        uint32_t Bh = sb + 32768 + bs * 20480;
        uint32_t Bl = Bh + 10240;
#pragma unroll
        for (int k16 = 0; k16 < 2; k16++) {
            int kc = k16 * 2;
            uint32_t ah[2][4], al[2][4];
            uint32_t offA0 = rowA0 * 64 + ((unsigned)((kc + kmatA) ^ sA0) << 4);
            uint32_t offA1 = rowA1 * 64 + ((unsigned)((kc + kmatA) ^ sA1) << 4);
            ldm4(ah[0][0], ah[0][1], ah[0][2], ah[0][3], Ah + offA0);
            ldm4(ah[1][0], ah[1][1], ah[1][2], ah[1][3], Ah + offA1);
            ldm4(al[0][0], al[0][1], al[0][2], al[0][3], Al + offA0);
            ldm4(al[1][0], al[1][1], al[1][2], al[1][3], Al + offA1);
#pragma unroll
            for (int np = 0; np < 5; np++) {
                int rowB = rowBb + np * 16;
                uint32_t offB = rowB * 64 + ((unsigned)((kc + kmatB) ^ ((rowB >> 1) & 3)) << 4);
                uint32_t bh[4], bl[4];
                ldm4(bh[0], bh[1], bh[2], bh[3], Bh + offB);
                ldm4(bl[0], bl[1], bl[2], bl[3], Bl + offB);
#pragma unroll
                for (int sub = 0; sub < 2; sub++) {
                    int ni = np * 2 + sub;
                    uint32_t h0 = bh[sub * 2], h1 = bh[sub * 2 + 1];
                    uint32_t l0 = bl[sub * 2], l1 = bl[sub * 2 + 1];
#pragma unroll
                    for (int mi = 0; mi < 2; mi++) {
                        mma16816(acc[mi][ni], ah[mi][0], ah[mi][1], ah[mi][2], ah[mi][3], h0, h1);
                        mma16816(acc[mi][ni], ah[mi][0], ah[mi][1], ah[mi][2], ah[mi][3], l0, l1);
                        mma16816(acc[mi][ni], al[mi][0], al[mi][1], al[mi][2], al[mi][3], h0, h1);
                    }
                }
            }
        }
        __syncthreads();
    }

    // epilogue: stage through smem, coalesced [co][pixel] stores
    float* DT = (float*)smc;
    int crow = lane >> 2;
#pragma unroll 1
    for (int h = 0; h < 2; h++) {
        if (wn == h) {
#pragma unroll
            for (int mi = 0; mi < 2; mi++)
#pragma unroll
                for (int ni = 0; ni < 10; ni++) {
                    int mb = m0 + mi * 16 + crow;
                    int nb = ni * 8 + (lane & 3) * 2;
                    DT[mb * 80 + nb]           = acc[mi][ni][0];
                    DT[mb * 80 + nb + 1]       = acc[mi][ni][1];
                    DT[(mb + 8) * 80 + nb]     = acc[mi][ni][2];
                    DT[(mb + 8) * 80 + nb + 1] = acc[mi][ni][3];
                }
        }
        __syncthreads();
        for (int idx = tid; idx < 10240; idx += 256) {
            int m = idx & 127, nl = idx >> 7;
            int co = h * 80 + nl;
            int p = p0 + m;
            if (co < HID && p < NPIX) {
                float v = fmaxf(DT[m * 80 + nl] + bias[co], 0.f);
                g_h2[((size_t)b * HID + co) * NPIX + p] = v;
            }
        }
        __syncthreads();
    }
}

// ---------------- trans (72ch) + reward conv, scalar f32x2 (unchanged) ----------------
__global__ __launch_bounds__(512) void trans_kernel(const float* __restrict__ tw,
                                                    const float* __restrict__ rw) {
    int b = blockIdx.y;
    int r0 = blockIdx.x * 3;
    __shared__ __align__(16) float tile[CI_BLK * 5 * 53];
    __shared__ __align__(16) float ws[CI_BLK * 9 * 90];
    int tid = threadIdx.x;
    int col = tid % HP;
    int g = tid / HP;
    bool act = tid < 9 * HP;

    u64   acc[3][4];
    float acc8[3];
#pragma unroll
    for (int r = 0; r < 3; r++) {
#pragma unroll
        for (int j = 0; j < 4; j++) acc[r][j] = 0ULL;
        acc8[r] = 0.f;
    }

    for (int cib = 0; cib < HID; cib += CI_BLK) {
        for (int i = tid; i < CI_BLK * 5 * 53; i += 512) {
            int ci = i / 265;
            int rem = i % 265;
            int rr = rem / 53, cc = rem % 53;
            int gr = r0 + rr - 2, gc = cc - 2;
            float v = 0.f;
            if (gr >= 0 && gr < GG && gc >= 0 && gc < GG)
                v = g_h2[(b * HID + cib + ci) * NPIX + gr * GG + gc];
            tile[i] = v;
        }
        for (int i = tid; i < CI_BLK * 9 * 90; i += 512) {
            int ci = i / 810;
            int rem = i % 810;
            int k = rem / 90, chp = rem % 90;
            int gg2 = chp / 10, j = chp % 10;
            float v = 0.f;
            if (j < 9) {
                int ch = gg2 * 9 + j;
                if (ch < 72) v = tw[ch * (HID * 9) + (cib + ci) * 9 + k];
                else if (ch == 72) v = rw[(cib + ci) * 9 + k];
            }
            ws[(ci * 9 + k) * 90 + chp] = v;
        }
        __syncthreads();
        if (act) {
            for (int ci = 0; ci < CI_BLK; ci++) {
                const float* tb = &tile[ci * 265 + col];
#pragma unroll
                for (int dc = 0; dc < 3; dc++) {
                    u64 pp[5];
                    float pf[5];
#pragma unroll
                    for (int r = 0; r < 5; r++) {
                        pf[r] = tb[r * 53 + dc];
                        pp[r] = pack2(pf[r], pf[r]);
                    }
#pragma unroll
                    for (int dr = 0; dr < 3; dr++) {
                        const float* wvf = &ws[(ci * 9 + dr * 3 + dc) * 90 + g * 10];
                        const u64* wp = (const u64*)wvf;
                        u64 w0 = wp[0], w1 = wp[1], w2 = wp[2], w3 = wp[3];
                        float w8 = wvf[8];
#pragma unroll
                        for (int rr = 0; rr < 3; rr++) {
                            u64 pv = pp[rr + dr];
                            ffma2(acc[rr][0], pv, w0);
                            ffma2(acc[rr][1], pv, w1);
                            ffma2(acc[rr][2], pv, w2);
                            ffma2(acc[rr][3], pv, w3);
                            acc8[rr] = fmaf(pf[rr + dr], w8, acc8[rr]);
                        }
                    }
                }
            }
        }
        __syncthreads();
    }
    if (act) {
#pragma unroll
        for (int rr = 0; rr < 3; rr++) {
            int p = (r0 + rr) * HP + col;
            float av[9];
#pragma unroll
            for (int j = 0; j < 4; j++) {
                float2 v = unpack2(acc[rr][j]);
                av[2 * j] = v.x;
                av[2 * j + 1] = v.y;
            }
            av[8] = acc8[rr];
            if (g < 8) {
                float m = av[0];
#pragma unroll
                for (int j = 1; j < 9; j++) m = fmaxf(m, av[j]);
                float e[9];
                float s = 0.f;
#pragma unroll
                for (int j = 0; j < 9; j++) { e[j] = expf(av[j] - m); s += e[j]; }
                float inv = 1.0f / s;
#pragma unroll
                for (int j = 0; j < 9; j++)
                    g_sT[((b * AA + g) * 9 + j) * (HP * HP) + p] = e[j] * inv;
            } else {
                g_reward[b * HP * HP + p] = av[0];
            }
        }
    }
}

// ---------------- VI loop (unchanged) ----------------
__global__ __launch_bounds__(1024) void vi_kernel() {
    int b = blockIdx.x;
    __shared__ float vpad[53 * 53];
    __shared__ float rsh[HP * HP];
    int tid = threadIdx.x;
    for (int i = tid; i < 53 * 53; i += 1024) vpad[i] = 0.f;
    for (int i = tid; i < HP * HP; i += 1024) rsh[i] = g_reward[b * HP * HP + i];
    const float* __restrict__ sb = &g_sT[(size_t)b * AA * 9 * HP * HP];

    for (int it = 0; it < KK; it++) {
        __syncthreads();
        float vnew[3];
#pragma unroll
        for (int j = 0; j < 3; j++) {
            int p = tid + j * 1024;
            if (p < HP * HP) {
                int r = p / HP, c = p % HP;
                float patch[9];
#pragma unroll
                for (int k = 0; k < 9; k++)
                    patch[k] = vpad[(r + k / 3) * 53 + (c + k % 3)];
                float rwv = rsh[p];
                float vm = -3.4e38f;
#pragma unroll
                for (int a = 0; a < AA; a++) {
                    float q = rwv;
#pragma unroll
                    for (int k = 0; k < 9; k++)
                        q = fmaf(sb[(a * 9 + k) * (HP * HP) + p], patch[k], q);
                    vm = fmaxf(vm, q);
                    if (it == KK - 1 && r < GG && c < GG)
                        g_qc[((b * AA + a) * GG + r) * GG + c] = q;
                }
                vnew[j] = vm;
            }
        }
        __syncthreads();
#pragma unroll
        for (int j = 0; j < 3; j++) {
            int p = tid + j * 1024;
            if (p < HP * HP) {
                int r = p / HP, c = p % HP;
                vpad[(r + 1) * 53 + (c + 1)] = vnew[j];
            }
        }
    }
}

// ---------------- head (unchanged) ----------------
__global__ __launch_bounds__(256) void head_kernel(const float* __restrict__ w1,
                                                   const float* __restrict__ b1g,
                                                   const float* __restrict__ w2,
                                                   const float* __restrict__ b2g,
                                                   float* __restrict__ out) {
    int b = blockIdx.y;
    int p = blockIdx.x * 256 + threadIdx.x;
    __shared__ float w1s[HID * AA];
    __shared__ float b1s[HID];
    __shared__ float w2s[HID * AA];
    __shared__ float b2s[AA];
    int tid = threadIdx.x;
    for (int i = tid; i < HID * AA; i += 256) w1s[i] = w1[i];
    for (int i = tid; i < HID; i += 256) b1s[i] = b1g[i];
    for (int i = tid; i < HID * AA; i += 256) {
        int a = i / HID, c = i % HID;
        w2s[c * AA + a] = w2[i];
    }
    for (int i = tid; i < AA; i += 256) b2s[i] = b2g[i];
    __syncthreads();
    if (p >= NPIX) return;

    float qv[AA];
#pragma unroll
    for (int a = 0; a < AA; a++) qv[a] = g_qc[(b * AA + a) * NPIX + p];
    float o[AA];
#pragma unroll
    for (int a = 0; a < AA; a++) o[a] = b2s[a];

    for (int c = 0; c < HID; c++) {
        const float2* wp1 = (const float2*)&w1s[c * 8];
        float m = b1s[c];
#pragma unroll
        for (int j = 0; j < 4; j++) {
            float2 ww = wp1[j];
            m = fmaf(qv[2 * j], ww.x, m);
            m = fmaf(qv[2 * j + 1], ww.y, m);
        }
        m = fmaxf(m, 0.f);
        const float2* wp2 = (const float2*)&w2s[c * 8];
#pragma unroll
        for (int j = 0; j < 4; j++) {
            float2 ww = wp2[j];
            o[2 * j]     = fmaf(m, ww.x, o[2 * j]);
            o[2 * j + 1] = fmaf(m, ww.y, o[2 * j + 1]);
        }
    }
#pragma unroll
    for (int a = 0; a < AA; a++)
        out[(b * AA + a) * NPIX + p] = o[a];
}

// ---------------- launch ----------------
extern "C" void kernel_launch(void* const* d_in, const int* in_sizes, int n_in,
                              void* d_out, int out_size) {
    const float* grid_in = (const float*)d_in[0];
    const float* h1_w = (const float*)d_in[3];
    const float* h1_b = (const float*)d_in[4];
    const float* h2_w = (const float*)d_in[5];
    const float* h2_b = (const float*)d_in[6];
    const float* r_w  = (const float*)d_in[7];
    const float* t_w  = (const float*)d_in[8];
    const float* a1_w = (const float*)d_in[9];
    const float* a1_b = (const float*)d_in[10];
    const float* a2_w = (const float*)d_in[11];
    const float* a2_b = (const float*)d_in[12];

    cudaFuncSetAttribute(conv2_mma_kernel, cudaFuncAttributeMaxDynamicSharedMemorySize, C2_SMEM);

    wsplit_kernel<<<(9 * 160 * 160 + 255) / 256, 256>>>(h2_w);
    conv1_kernel<<<dim3(7, BB), 256>>>(grid_in, h1_w, h1_b);
    h1split_kernel<<<dim3(38, 1, BB), 256>>>();
    conv2_mma_kernel<<<dim3((NPIX + 127) / 128, BB), 256, C2_SMEM>>>(h2_b);
    trans_kernel<<<dim3(17, BB), 512>>>(t_w, r_w);
    vi_kernel<<<BB, 1024>>>();
    head_kernel<<<dim3(10, BB), 256>>>(a1_w, a1_b, a2_w, a2_b, (float*)d_out);
}

// round 14
// speedup vs baseline: 1.9295x; 1.4738x over previous
#include <cuda_runtime.h>
#include <cuda_bf16.h>
#include <cstdint>

#define GG  49
#define HP  51
#define HID 150
#define BB  128
#define CC  2
#define AA  8
#define KK  30
#define NPIX (GG * GG)          // 2401
#define NPT  (HP * HP)          // 2601

typedef unsigned long long u64;

// ---------------- mma / ldmatrix / cp.async (compute_80 baseline) ----------------
__device__ __forceinline__ void mma16816(float* d,
                                         uint32_t a0, uint32_t a1, uint32_t a2, uint32_t a3,
                                         uint32_t b0, uint32_t b1) {
    asm volatile(
        "mma.sync.aligned.m16n8k16.row.col.f32.bf16.bf16.f32 "
        "{%0,%1,%2,%3}, {%4,%5,%6,%7}, {%8,%9}, {%0,%1,%2,%3};"
        : "+f"(d[0]), "+f"(d[1]), "+f"(d[2]), "+f"(d[3])
        : "r"(a0), "r"(a1), "r"(a2), "r"(a3), "r"(b0), "r"(b1));
}
__device__ __forceinline__ void ldm4(uint32_t& r0, uint32_t& r1, uint32_t& r2, uint32_t& r3,
                                     uint32_t addr) {
    asm volatile("ldmatrix.sync.aligned.m8n8.x4.shared.b16 {%0,%1,%2,%3}, [%4];"
                 : "=r"(r0), "=r"(r1), "=r"(r2), "=r"(r3) : "r"(addr));
}
__device__ __forceinline__ void ldm2(uint32_t& r0, uint32_t& r1, uint32_t addr) {
    asm volatile("ldmatrix.sync.aligned.m8n8.x2.shared.b16 {%0,%1}, [%2];"
                 : "=r"(r0), "=r"(r1) : "r"(addr));
}
__device__ __forceinline__ void cp16(uint32_t dst, const void* src, int sz) {
    asm volatile("cp.async.cg.shared.global [%0], [%1], 16, %2;"
                 :: "r"(dst), "l"(src), "r"(sz));
}
__device__ __forceinline__ uint32_t smem_u32(const void* p) {
    uint32_t a;
    asm("{ .reg .u64 t; cvta.to.shared.u64 t, %1; cvt.u32.u64 %0, t; }" : "=r"(a) : "l"(p));
    return a;
}

// ---------------- scratch ----------------
__device__ float g_h1[BB * HID * NPIX];
__device__ float g_sT[BB * AA * 9 * NPT];
__device__ float g_reward[BB * NPT];
__device__ float g_qc[BB * AA * NPIX];
// channel-last bf16 hi/lo planes: [b][pix][160]
__device__ __nv_bfloat16 g_h1h[(size_t)BB * NPIX * 160];
__device__ __nv_bfloat16 g_h1l[(size_t)BB * NPIX * 160];
__device__ __nv_bfloat16 g_h2h[(size_t)BB * NPIX * 160];
__device__ __nv_bfloat16 g_h2l[(size_t)BB * NPIX * 160];
// pre-split weights: conv2 [t][n(160)][ci(160)], trans [t][n(80)][ci(160)]
__device__ __nv_bfloat16 g_wh[9 * 160 * 160];
__device__ __nv_bfloat16 g_wl[9 * 160 * 160];
__device__ __nv_bfloat16 g_twh[9 * 80 * 160];
__device__ __nv_bfloat16 g_twl[9 * 80 * 160];

// ---------------- weight splits ----------------
__global__ __launch_bounds__(256) void wsplit_kernel(const float* __restrict__ w) {
    int idx = blockIdx.x * 256 + threadIdx.x;
    if (idx >= 9 * 160 * 160) return;
    int ci = idx % 160;
    int rest = idx / 160;
    int n = rest % 160;
    int t = rest / 160;
    float v = 0.f;
    if (n < HID && ci < HID) v = w[n * (HID * 9) + ci * 9 + t];
    __nv_bfloat16 h = __float2bfloat16(v);
    g_wh[idx] = h;
    g_wl[idx] = __float2bfloat16(v - __bfloat162float(h));
}
__global__ __launch_bounds__(256) void wsplit2_kernel(const float* __restrict__ tw,
                                                      const float* __restrict__ rw) {
    int idx = blockIdx.x * 256 + threadIdx.x;
    if (idx >= 9 * 80 * 160) return;
    int ci = idx % 160;
    int rest = idx / 160;
    int n = rest % 80;
    int t = rest / 80;
    float v = 0.f;
    if (ci < HID) {
        if (n < 72) v = tw[n * (HID * 9) + ci * 9 + t];
        else if (n == 72) v = rw[ci * 9 + t];
    }
    __nv_bfloat16 h = __float2bfloat16(v);
    g_twh[idx] = h;
    g_twl[idx] = __float2bfloat16(v - __bfloat162float(h));
}

// ---------------- h1 transpose + split ----------------
__global__ __launch_bounds__(256) void h1split_kernel() {
    int b = blockIdx.z;
    int p0 = blockIdx.x * 64;
    __shared__ float ts[160][65];
    int tid = threadIdx.x;
    for (int i = tid; i < 160 * 64; i += 256) {
        int ci = i >> 6, pl = i & 63;
        float v = 0.f;
        int p = p0 + pl;
        if (ci < HID && p < NPIX) v = g_h1[((size_t)b * HID + ci) * NPIX + p];
        ts[ci][pl] = v;
    }
    __syncthreads();
    for (int i = tid; i < 64 * 160; i += 256) {
        int pl = i / 160, ci = i % 160;
        int p = p0 + pl;
        if (p < NPIX) {
            float v = ts[ci][pl];
            __nv_bfloat16 h = __float2bfloat16(v);
            size_t o = ((size_t)b * NPIX + p) * 160 + ci;
            g_h1h[o] = h;
            g_h1l[o] = __float2bfloat16(v - __bfloat162float(h));
        }
    }
}

// ---------------- conv1 (unchanged) ----------------
__global__ __launch_bounds__(256) void conv1_kernel(const float* __restrict__ gin,
                                                    const float* __restrict__ w,
                                                    const float* __restrict__ bias) {
    int b = blockIdx.y;
    int r0 = blockIdx.x * 7;
    __shared__ float tile[CC * 9 * 51];
    __shared__ float ws[HID * 18];
    __shared__ float bs[HID];
    int tid = threadIdx.x;

    for (int i = tid; i < CC * 9 * 51; i += 256) {
        int ci = i / (9 * 51);
        int rr = (i / 51) % 9;
        int cc = i % 51;
        int gr = r0 + rr - 1, gc = cc - 1;
        float v = 0.f;
        if (gr >= 0 && gr < GG && gc >= 0 && gc < GG)
            v = gin[(b * CC + ci) * NPIX + gr * GG + gc];
        tile[i] = v;
    }
    for (int i = tid; i < HID * 18; i += 256) ws[i] = w[i];
    for (int i = tid; i < HID; i += 256) bs[i] = bias[i];
    __syncthreads();

    for (int pp = tid; pp < 7 * GG; pp += 256) {
        int lr = pp / GG, lc = pp % GG;
        int gr = r0 + lr;
        if (gr >= GG) continue;
        float patch[18];
#pragma unroll
        for (int ci = 0; ci < CC; ci++)
#pragma unroll
            for (int k = 0; k < 9; k++)
                patch[ci * 9 + k] = tile[ci * 9 * 51 + (lr + k / 3) * 51 + (lc + k % 3)];
        for (int co = 0; co < HID; co++) {
            float a = bs[co];
            const float2* wp = (const float2*)&ws[co * 18];
#pragma unroll
            for (int j = 0; j < 9; j++) {
                float2 w2 = wp[j];
                a = fmaf(patch[2 * j], w2.x, a);
                a = fmaf(patch[2 * j + 1], w2.y, a);
            }
            g_h1[(b * HID + co) * NPIX + gr * GG + lc] = fmaxf(a, 0.f);
        }
    }
}

// ---------------- conv2: mma.sync bf16 3-term, cp.async double-buffer, ldmatrix ----------------
// smem: A[2buf][2pl][128x64B]=32KB at 0, B[2buf][2pl][160x64B]=40KB at 32768. 72KB.
#define C2_SMEM 73728

__global__ void __launch_bounds__(256, 2) conv2_mma_kernel(const float* __restrict__ bias) {
    extern __shared__ char smc[];
    uint32_t sb = smem_u32(smc);
    int tid = threadIdx.x;
    int lane = tid & 31, wid = tid >> 5;
    int b = blockIdx.y;
    int p0 = blockIdx.x * 128;
    int m0 = (wid & 3) * 32;
    int wn = wid >> 2;
    int n0 = wn * 80;

    int mrow = tid & 127;
    int aplane = tid >> 7;
    int pa = p0 + mrow; if (pa > NPIX - 1) pa = NPIX - 1;
    int par = pa / GG, pac = pa % GG;
    const __nv_bfloat16* abase = (aplane ? g_h1l : g_h1h) + (size_t)b * NPIX * 160;
    uint32_t adst0 = sb + aplane * 8192 + mrow * 64;
    int aswz = (mrow >> 1) & 3;

    int mat = lane >> 3, wl = lane & 7;
    int rowA0 = m0 + ((mat & 1) << 3) + wl;
    int rowA1 = rowA0 + 16;
    int sA0 = (rowA0 >> 1) & 3;
    int sA1 = (rowA1 >> 1) & 3;
    int kmatA = mat >> 1;
    int rowBb = n0 + (((mat >> 1) & 1) << 3) + wl;
    int kmatB = mat & 1;

    float acc[2][10][4];
#pragma unroll
    for (int mi = 0; mi < 2; mi++)
#pragma unroll
        for (int ni = 0; ni < 10; ni++)
#pragma unroll
            for (int j = 0; j < 4; j++) acc[mi][ni][j] = 0.f;

    auto load_stage = [&](int s, int bs) {
        int t = s / 5;
        int cb = (s - t * 5) * 32;
        int dr = t / 3 - 1, dc = t - (t / 3) * 3 - 1;
        int rr = par + dr, cc = pac + dc;
        bool val = ((unsigned)rr < GG) && ((unsigned)cc < GG);
        const __nv_bfloat16* src = abase + (size_t)(val ? (rr * GG + cc) : 0) * 160 + cb;
        int sz = val ? 16 : 0;
        uint32_t d = adst0 + bs * 16384;
#pragma unroll
        for (int j = 0; j < 4; j++)
            cp16(d + (((unsigned)(j ^ aswz)) << 4), (const char*)src + j * 16, sz);
        for (int rp = tid; rp < 320; rp += 256) {
            int bp = rp >= 160 ? 1 : 0;
            int n = rp - bp * 160;
            const __nv_bfloat16* wsrc = (bp ? g_wl : g_wh) + (size_t)(t * 160 + n) * 160 + cb;
            uint32_t bd = sb + 32768 + bs * 20480 + bp * 10240 + n * 64;
            int bsw = (n >> 1) & 3;
#pragma unroll
            for (int j = 0; j < 4; j++)
                cp16(bd + (((unsigned)(j ^ bsw)) << 4), (const char*)wsrc + j * 16, 16);
        }
        asm volatile("cp.async.commit_group;" ::: "memory");
    };

    load_stage(0, 0);
    for (int s = 0; s < 45; s++) {
        int bs = s & 1;
        if (s + 1 < 45) {
            load_stage(s + 1, (s + 1) & 1);
            asm volatile("cp.async.wait_group 1;" ::: "memory");
        } else {
            asm volatile("cp.async.wait_group 0;" ::: "memory");
        }
        __syncthreads();
        uint32_t Ah = sb + bs * 16384;
        uint32_t Al = Ah + 8192;
        uint32_t Bh = sb + 32768 + bs * 20480;
        uint32_t Bl = Bh + 10240;
#pragma unroll
        for (int k16 = 0; k16 < 2; k16++) {
            int kc = k16 * 2;
            uint32_t ah[2][4], al[2][4];
            uint32_t offA0 = rowA0 * 64 + ((unsigned)((kc + kmatA) ^ sA0) << 4);
            uint32_t offA1 = rowA1 * 64 + ((unsigned)((kc + kmatA) ^ sA1) << 4);
            ldm4(ah[0][0], ah[0][1], ah[0][2], ah[0][3], Ah + offA0);
            ldm4(ah[1][0], ah[1][1], ah[1][2], ah[1][3], Ah + offA1);
            ldm4(al[0][0], al[0][1], al[0][2], al[0][3], Al + offA0);
            ldm4(al[1][0], al[1][1], al[1][2], al[1][3], Al + offA1);
#pragma unroll
            for (int np = 0; np < 5; np++) {
                int rowB = rowBb + np * 16;
                uint32_t offB = rowB * 64 + ((unsigned)((kc + kmatB) ^ ((rowB >> 1) & 3)) << 4);
                uint32_t bh[4], bl[4];
                ldm4(bh[0], bh[1], bh[2], bh[3], Bh + offB);
                ldm4(bl[0], bl[1], bl[2], bl[3], Bl + offB);
#pragma unroll
                for (int sub = 0; sub < 2; sub++) {
                    int ni = np * 2 + sub;
                    uint32_t h0 = bh[sub * 2], h1 = bh[sub * 2 + 1];
                    uint32_t l0 = bl[sub * 2], l1 = bl[sub * 2 + 1];
#pragma unroll
                    for (int mi = 0; mi < 2; mi++) {
                        mma16816(acc[mi][ni], ah[mi][0], ah[mi][1], ah[mi][2], ah[mi][3], h0, h1);
                        mma16816(acc[mi][ni], ah[mi][0], ah[mi][1], ah[mi][2], ah[mi][3], l0, l1);
                        mma16816(acc[mi][ni], al[mi][0], al[mi][1], al[mi][2], al[mi][3], h0, h1);
                    }
                }
            }
        }
        __syncthreads();
    }

    // epilogue: stage through smem; bias+relu; split to bf16 hi/lo channel-last planes
    float* DT = (float*)smc;
    int crow = lane >> 2;
#pragma unroll 1
    for (int h = 0; h < 2; h++) {
        if (wn == h) {
#pragma unroll
            for (int mi = 0; mi < 2; mi++)
#pragma unroll
                for (int ni = 0; ni < 10; ni++) {
                    int mb = m0 + mi * 16 + crow;
                    int nb = ni * 8 + (lane & 3) * 2;
                    DT[mb * 80 + nb]           = acc[mi][ni][0];
                    DT[mb * 80 + nb + 1]       = acc[mi][ni][1];
                    DT[(mb + 8) * 80 + nb]     = acc[mi][ni][2];
                    DT[(mb + 8) * 80 + nb + 1] = acc[mi][ni][3];
                }
        }
        __syncthreads();
        for (int idx = tid; idx < 1280; idx += 256) {
            int m = idx / 10, j = idx % 10;
            int p = p0 + m;
            if (p >= NPIX) continue;
            uint32_t hw[4], lw[4];
#pragma unroll
            for (int e2 = 0; e2 < 4; e2++) {
                uint32_t hpair = 0, lpair = 0;
#pragma unroll
                for (int q = 0; q < 2; q++) {
                    int co = h * 80 + j * 8 + e2 * 2 + q;
                    float v = 0.f;
                    if (co < HID) v = fmaxf(DT[m * 80 + j * 8 + e2 * 2 + q] + __ldg(&bias[co]), 0.f);
                    __nv_bfloat16 hx = __float2bfloat16(v);
                    float lo = v - __bfloat162float(hx);
                    __nv_bfloat16 lx = __float2bfloat16(lo);
                    hpair |= (uint32_t)__bfloat16_as_ushort(hx) << (16 * q);
                    lpair |= (uint32_t)__bfloat16_as_ushort(lx) << (16 * q);
                }
                hw[e2] = hpair;
                lw[e2] = lpair;
            }
            size_t off = ((size_t)b * NPIX + p) * 160 + h * 80 + j * 8;
            *(uint4*)&g_h2h[off] = make_uint4(hw[0], hw[1], hw[2], hw[3]);
            *(uint4*)&g_h2l[off] = make_uint4(lw[0], lw[1], lw[2], lw[3]);
        }
        __syncthreads();
    }
}

// ---------------- trans: same mma pipeline, N=80, pad=2, fused softmax epilogue ----------------
// smem: A[2buf][2pl][128x64B]=32KB at 0, B[2buf][2pl][80x64B]=20KB at 32768. 53248 B.
#define TR_SMEM 53248

__global__ void __launch_bounds__(256, 2) trans_mma_kernel() {
    extern __shared__ char smc[];
    uint32_t sb = smem_u32(smc);
    int tid = threadIdx.x;
    int lane = tid & 31, wid = tid >> 5;
    int b = blockIdx.y;
    int p0 = blockIdx.x * 128;
    int m0 = (wid & 3) * 32;
    int wn = wid >> 2;
    int n0 = wn * 40;

    int mrow = tid & 127;
    int aplane = tid >> 7;
    int pa = p0 + mrow;
    bool pvalid = pa < NPT;
    int pc = pvalid ? pa : NPT - 1;
    int par = pc / HP, pac = pc % HP;
    const __nv_bfloat16* abase = (aplane ? g_h2l : g_h2h) + (size_t)b * NPIX * 160;
    uint32_t adst0 = sb + aplane * 8192 + mrow * 64;
    int aswz = (mrow >> 1) & 3;

    int mat = lane >> 3, wl = lane & 7;
    int rowA0 = m0 + ((mat & 1) << 3) + wl;
    int rowA1 = rowA0 + 16;
    int sA0 = (rowA0 >> 1) & 3;
    int sA1 = (rowA1 >> 1) & 3;
    int kmatA = mat >> 1;
    int rowBb = n0 + (((mat >> 1) & 1) << 3) + wl;
    int kmatB = mat & 1;
    int rowT = n0 + 32 + wl;
    int kmatT = (lane >> 3) & 1;
    int sT = (rowT >> 1) & 3;

    float acc[2][5][4];
#pragma unroll
    for (int mi = 0; mi < 2; mi++)
#pragma unroll
        for (int ni = 0; ni < 5; ni++)
#pragma unroll
            for (int j = 0; j < 4; j++) acc[mi][ni][j] = 0.f;

    auto load_stage = [&](int s, int bs) {
        int t = s / 5;
        int cb = (s - t * 5) * 32;
        int dr = t / 3 - 2, dc = t - (t / 3) * 3 - 2;
        int rr = par + dr, cc = pac + dc;
        bool val = pvalid && ((unsigned)rr < GG) && ((unsigned)cc < GG);
        const __nv_bfloat16* src = abase + (size_t)(val ? (rr * GG + cc) : 0) * 160 + cb;
        int sz = val ? 16 : 0;
        uint32_t d = adst0 + bs * 16384;
#pragma unroll
        for (int j = 0; j < 4; j++)
            cp16(d + (((unsigned)(j ^ aswz)) << 4), (const char*)src + j * 16, sz);
        if (tid < 160) {
            int bp = tid >= 80 ? 1 : 0;
            int n = tid - bp * 80;
            const __nv_bfloat16* wsrc = (bp ? g_twl : g_twh) + (size_t)(t * 80 + n) * 160 + cb;
            uint32_t bd = sb + 32768 + bs * 10240 + bp * 5120 + n * 64;
            int bsw = (n >> 1) & 3;
#pragma unroll
            for (int j = 0; j < 4; j++)
                cp16(bd + (((unsigned)(j ^ bsw)) << 4), (const char*)wsrc + j * 16, 16);
        }
        asm volatile("cp.async.commit_group;" ::: "memory");
    };

    load_stage(0, 0);
    for (int s = 0; s < 45; s++) {
        int bs = s & 1;
        if (s + 1 < 45) {
            load_stage(s + 1, (s + 1) & 1);
            asm volatile("cp.async.wait_group 1;" ::: "memory");
        } else {
            asm volatile("cp.async.wait_group 0;" ::: "memory");
        }
        __syncthreads();
        uint32_t Ah = sb + bs * 16384;
        uint32_t Al = Ah + 8192;
        uint32_t Bh = sb + 32768 + bs * 10240;
        uint32_t Bl = Bh + 5120;
#pragma unroll
        for (int k16 = 0; k16 < 2; k16++) {
            int kc = k16 * 2;
            uint32_t ah[2][4], al[2][4];
            uint32_t offA0 = rowA0 * 64 + ((unsigned)((kc + kmatA) ^ sA0) << 4);
            uint32_t offA1 = rowA1 * 64 + ((unsigned)((kc + kmatA) ^ sA1) << 4);
            ldm4(ah[0][0], ah[0][1], ah[0][2], ah[0][3], Ah + offA0);
            ldm4(ah[1][0], ah[1][1], ah[1][2], ah[1][3], Ah + offA1);
            ldm4(al[0][0], al[0][1], al[0][2], al[0][3], Al + offA0);
            ldm4(al[1][0], al[1][1], al[1][2], al[1][3], Al + offA1);
#pragma unroll
            for (int np = 0; np < 2; np++) {
                int rowB = rowBb + np * 16;
                uint32_t offB = rowB * 64 + ((unsigned)((kc + kmatB) ^ ((rowB >> 1) & 3)) << 4);
                uint32_t bh[4], bl[4];
                ldm4(bh[0], bh[1], bh[2], bh[3], Bh + offB);
                ldm4(bl[0], bl[1], bl[2], bl[3], Bl + offB);
#pragma unroll
                for (int sub = 0; sub < 2; sub++) {
                    int ni = np * 2 + sub;
                    uint32_t h0 = bh[sub * 2], h1 = bh[sub * 2 + 1];
                    uint32_t l0 = bl[sub * 2], l1 = bl[sub * 2 + 1];
#pragma unroll
                    for (int mi = 0; mi < 2; mi++) {
                        mma16816(acc[mi][ni], ah[mi][0], ah[mi][1], ah[mi][2], ah[mi][3], h0, h1);
                        mma16816(acc[mi][ni], ah[mi][0], ah[mi][1], ah[mi][2], ah[mi][3], l0, l1);
                        mma16816(acc[mi][ni], al[mi][0], al[mi][1], al[mi][2], al[mi][3], h0, h1);
                    }
                }
            }
            // tail n8 tile (ni = 4)
            {
                uint32_t offT = rowT * 64 + ((unsigned)((kc + kmatT) ^ sT) << 4);
                uint32_t th0, th1, tl0, tl1;
                ldm2(th0, th1, Bh + offT);
                ldm2(tl0, tl1, Bl + offT);
#pragma unroll
                for (int mi = 0; mi < 2; mi++) {
                    mma16816(acc[mi][4], ah[mi][0], ah[mi][1], ah[mi][2], ah[mi][3], th0, th1);
                    mma16816(acc[mi][4], ah[mi][0], ah[mi][1], ah[mi][2], ah[mi][3], tl0, tl1);
                    mma16816(acc[mi][4], al[mi][0], al[mi][1], al[mi][2], al[mi][3], th0, th1);
                }
            }
        }
        __syncthreads();
    }

    // epilogue: stage D[128 x 80], per-pixel softmax over 8 groups of 9 + reward
    float* DT = (float*)smc;
    int crow = lane >> 2;
#pragma unroll
    for (int mi = 0; mi < 2; mi++)
#pragma unroll
        for (int ni = 0; ni < 5; ni++) {
            int mb = m0 + mi * 16 + crow;
            int nb = n0 + ni * 8 + (lane & 3) * 2;
            DT[mb * 80 + nb]           = acc[mi][ni][0];
            DT[mb * 80 + nb + 1]       = acc[mi][ni][1];
            DT[(mb + 8) * 80 + nb]     = acc[mi][ni][2];
            DT[(mb + 8) * 80 + nb + 1] = acc[mi][ni][3];
        }
    __syncthreads();
    if (tid < 128) {
        int p = p0 + tid;
        if (p < NPT) {
            const float* row = &DT[tid * 80];
#pragma unroll
            for (int a = 0; a < AA; a++) {
                float av[9];
#pragma unroll
                for (int k = 0; k < 9; k++) av[k] = row[a * 9 + k];
                float m = av[0];
#pragma unroll
                for (int k = 1; k < 9; k++) m = fmaxf(m, av[k]);
                float e[9];
                float sum = 0.f;
#pragma unroll
                for (int k = 0; k < 9; k++) { e[k] = expf(av[k] - m); sum += e[k]; }
                float inv = 1.0f / sum;
#pragma unroll
                for (int k = 0; k < 9; k++)
                    g_sT[((b * AA + a) * 9 + k) * NPT + p] = e[k] * inv;
            }
            g_reward[b * NPT + p] = row[72];
        }
    }
}

// ---------------- VI loop (unchanged) ----------------
__global__ __launch_bounds__(1024) void vi_kernel() {
    int b = blockIdx.x;
    __shared__ float vpad[53 * 53];
    __shared__ float rsh[NPT];
    int tid = threadIdx.x;
    for (int i = tid; i < 53 * 53; i += 1024) vpad[i] = 0.f;
    for (int i = tid; i < NPT; i += 1024) rsh[i] = g_reward[b * NPT + i];
    const float* __restrict__ sb = &g_sT[(size_t)b * AA * 9 * NPT];

    for (int it = 0; it < KK; it++) {
        __syncthreads();
        float vnew[3];
#pragma unroll
        for (int j = 0; j < 3; j++) {
            int p = tid + j * 1024;
            if (p < NPT) {
                int r = p / HP, c = p % HP;
                float patch[9];
#pragma unroll
                for (int k = 0; k < 9; k++)
                    patch[k] = vpad[(r + k / 3) * 53 + (c + k % 3)];
                float rwv = rsh[p];
                float vm = -3.4e38f;
#pragma unroll
                for (int a = 0; a < AA; a++) {
                    float q = rwv;
#pragma unroll
                    for (int k = 0; k < 9; k++)
                        q = fmaf(sb[(a * 9 + k) * NPT + p], patch[k], q);
                    vm = fmaxf(vm, q);
                    if (it == KK - 1 && r < GG && c < GG)
                        g_qc[((b * AA + a) * GG + r) * GG + c] = q;
                }
                vnew[j] = vm;
            }
        }
        __syncthreads();
#pragma unroll
        for (int j = 0; j < 3; j++) {
            int p = tid + j * 1024;
            if (p < NPT) {
                int r = p / HP, c = p % HP;
                vpad[(r + 1) * 53 + (c + 1)] = vnew[j];
            }
        }
    }
}

// ---------------- head (unchanged) ----------------
__global__ __launch_bounds__(256) void head_kernel(const float* __restrict__ w1,
                                                   const float* __restrict__ b1g,
                                                   const float* __restrict__ w2,
                                                   const float* __restrict__ b2g,
                                                   float* __restrict__ out) {
    int b = blockIdx.y;
    int p = blockIdx.x * 256 + threadIdx.x;
    __shared__ float w1s[HID * AA];
    __shared__ float b1s[HID];
    __shared__ float w2s[HID * AA];
    __shared__ float b2s[AA];
    int tid = threadIdx.x;
    for (int i = tid; i < HID * AA; i += 256) w1s[i] = w1[i];
    for (int i = tid; i < HID; i += 256) b1s[i] = b1g[i];
    for (int i = tid; i < HID * AA; i += 256) {
        int a = i / HID, c = i % HID;
        w2s[c * AA + a] = w2[i];
    }
    for (int i = tid; i < AA; i += 256) b2s[i] = b2g[i];
    __syncthreads();
    if (p >= NPIX) return;

    float qv[AA];
#pragma unroll
    for (int a = 0; a < AA; a++) qv[a] = g_qc[(b * AA + a) * NPIX + p];
    float o[AA];
#pragma unroll
    for (int a = 0; a < AA; a++) o[a] = b2s[a];

    for (int c = 0; c < HID; c++) {
        const float2* wp1 = (const float2*)&w1s[c * 8];
        float m = b1s[c];
#pragma unroll
        for (int j = 0; j < 4; j++) {
            float2 ww = wp1[j];
            m = fmaf(qv[2 * j], ww.x, m);
            m = fmaf(qv[2 * j + 1], ww.y, m);
        }
        m = fmaxf(m, 0.f);
        const float2* wp2 = (const float2*)&w2s[c * 8];
#pragma unroll
        for (int j = 0; j < 4; j++) {
            float2 ww = wp2[j];
            o[2 * j]     = fmaf(m, ww.x, o[2 * j]);
            o[2 * j + 1] = fmaf(m, ww.y, o[2 * j + 1]);
        }
    }
#pragma unroll
    for (int a = 0; a < AA; a++)
        out[(b * AA + a) * NPIX + p] = o[a];
}

// ---------------- launch ----------------
extern "C" void kernel_launch(void* const* d_in, const int* in_sizes, int n_in,
                              void* d_out, int out_size) {
    const float* grid_in = (const float*)d_in[0];
    const float* h1_w = (const float*)d_in[3];
    const float* h1_b = (const float*)d_in[4];
    const float* h2_w = (const float*)d_in[5];
    const float* h2_b = (const float*)d_in[6];
    const float* r_w  = (const float*)d_in[7];
    const float* t_w  = (const float*)d_in[8];
    const float* a1_w = (const float*)d_in[9];
    const float* a1_b = (const float*)d_in[10];
    const float* a2_w = (const float*)d_in[11];
    const float* a2_b = (const float*)d_in[12];

    cudaFuncSetAttribute(conv2_mma_kernel, cudaFuncAttributeMaxDynamicSharedMemorySize, C2_SMEM);
    cudaFuncSetAttribute(trans_mma_kernel, cudaFuncAttributeMaxDynamicSharedMemorySize, TR_SMEM);

    wsplit_kernel<<<(9 * 160 * 160 + 255) / 256, 256>>>(h2_w);
    wsplit2_kernel<<<(9 * 80 * 160 + 255) / 256, 256>>>(t_w, r_w);
    conv1_kernel<<<dim3(7, BB), 256>>>(grid_in, h1_w, h1_b);
    h1split_kernel<<<dim3(38, 1, BB), 256>>>();
    conv2_mma_kernel<<<dim3((NPIX + 127) / 128, BB), 256, C2_SMEM>>>(h2_b);
    trans_mma_kernel<<<dim3((NPT + 127) / 128, BB), 256, TR_SMEM>>>();
    vi_kernel<<<BB, 1024>>>();
    head_kernel<<<dim3(10, BB), 256>>>(a1_w, a1_b, a2_w, a2_b, (float*)d_out);
}

// round 15
// speedup vs baseline: 1.9609x; 1.0163x over previous
#include <cuda_runtime.h>
#include <cuda_bf16.h>
#include <cstdint>

#define GG  49
#define HP  51
#define HID 150
#define BB  128
#define CC  2
#define AA  8
#define KK  30
#define NPIX (GG * GG)          // 2401
#define NPT  (HP * HP)          // 2601

// ---------------- mma / ldmatrix / cp.async (compute_80 baseline) ----------------
__device__ __forceinline__ void mma16816(float* d,
                                         uint32_t a0, uint32_t a1, uint32_t a2, uint32_t a3,
                                         uint32_t b0, uint32_t b1) {
    asm volatile(
        "mma.sync.aligned.m16n8k16.row.col.f32.bf16.bf16.f32 "
        "{%0,%1,%2,%3}, {%4,%5,%6,%7}, {%8,%9}, {%0,%1,%2,%3};"
        : "+f"(d[0]), "+f"(d[1]), "+f"(d[2]), "+f"(d[3])
        : "r"(a0), "r"(a1), "r"(a2), "r"(a3), "r"(b0), "r"(b1));
}
__device__ __forceinline__ void ldm4(uint32_t& r0, uint32_t& r1, uint32_t& r2, uint32_t& r3,
                                     uint32_t addr) {
    asm volatile("ldmatrix.sync.aligned.m8n8.x4.shared.b16 {%0,%1,%2,%3}, [%4];"
                 : "=r"(r0), "=r"(r1), "=r"(r2), "=r"(r3) : "r"(addr));
}
__device__ __forceinline__ void ldm2(uint32_t& r0, uint32_t& r1, uint32_t addr) {
    asm volatile("ldmatrix.sync.aligned.m8n8.x2.shared.b16 {%0,%1}, [%2];"
                 : "=r"(r0), "=r"(r1) : "r"(addr));
}
__device__ __forceinline__ void cp16(uint32_t dst, const void* src, int sz) {
    asm volatile("cp.async.cg.shared.global [%0], [%1], 16, %2;"
                 :: "r"(dst), "l"(src), "r"(sz));
}
__device__ __forceinline__ uint32_t smem_u32(const void* p) {
    uint32_t a;
    asm("{ .reg .u64 t; cvta.to.shared.u64 t, %1; cvt.u32.u64 %0, t; }" : "=r"(a) : "l"(p));
    return a;
}

// ---------------- scratch ----------------
__device__ float g_sT[BB * AA * 9 * NPT];
__device__ float g_reward[BB * NPT];
__device__ float g_qc[BB * AA * NPIX];
// channel-last bf16 hi/lo planes: [b][pix][160]  (tails 150..159 stay zero-init)
__device__ __nv_bfloat16 g_h1h[(size_t)BB * NPIX * 160];
__device__ __nv_bfloat16 g_h1l[(size_t)BB * NPIX * 160];
__device__ __nv_bfloat16 g_h2h[(size_t)BB * NPIX * 160];
__device__ __nv_bfloat16 g_h2l[(size_t)BB * NPIX * 160];
// pre-split weights: conv2 [t][n(160)][ci(160)], trans [t][n(80)][ci(160)]
__device__ __nv_bfloat16 g_wh[9 * 160 * 160];
__device__ __nv_bfloat16 g_wl[9 * 160 * 160];
__device__ __nv_bfloat16 g_twh[9 * 80 * 160];
__device__ __nv_bfloat16 g_twl[9 * 80 * 160];

// ---------------- weight splits ----------------
__global__ __launch_bounds__(256) void wsplit_kernel(const float* __restrict__ w) {
    int idx = blockIdx.x * 256 + threadIdx.x;
    if (idx >= 9 * 160 * 160) return;
    int ci = idx % 160;
    int rest = idx / 160;
    int n = rest % 160;
    int t = rest / 160;
    float v = 0.f;
    if (n < HID && ci < HID) v = w[n * (HID * 9) + ci * 9 + t];
    __nv_bfloat16 h = __float2bfloat16(v);
    g_wh[idx] = h;
    g_wl[idx] = __float2bfloat16(v - __bfloat162float(h));
}
__global__ __launch_bounds__(256) void wsplit2_kernel(const float* __restrict__ tw,
                                                      const float* __restrict__ rw) {
    int idx = blockIdx.x * 256 + threadIdx.x;
    if (idx >= 9 * 80 * 160) return;
    int ci = idx % 160;
    int rest = idx / 160;
    int n = rest % 80;
    int t = rest / 80;
    float v = 0.f;
    if (ci < HID) {
        if (n < 72) v = tw[n * (HID * 9) + ci * 9 + t];
        else if (n == 72) v = rw[ci * 9 + t];
    }
    __nv_bfloat16 h = __float2bfloat16(v);
    g_twh[idx] = h;
    g_twl[idx] = __float2bfloat16(v - __bfloat162float(h));
}

// ---------------- conv1: fused relu + bf16 hi/lo split, channel-last emit ----------------
__global__ __launch_bounds__(256) void conv1_kernel(const float* __restrict__ gin,
                                                    const float* __restrict__ w,
                                                    const float* __restrict__ bias) {
    int b = blockIdx.y;
    int r0 = blockIdx.x * 7;
    __shared__ float tile[CC * 9 * 51];
    __shared__ float ws[HID * 18];
    __shared__ float bs[HID];
    int tid = threadIdx.x;

    for (int i = tid; i < CC * 9 * 51; i += 256) {
        int ci = i / (9 * 51);
        int rr = (i / 51) % 9;
        int cc = i % 51;
        int gr = r0 + rr - 1, gc = cc - 1;
        float v = 0.f;
        if (gr >= 0 && gr < GG && gc >= 0 && gc < GG)
            v = gin[(b * CC + ci) * NPIX + gr * GG + gc];
        tile[i] = v;
    }
    for (int i = tid; i < HID * 18; i += 256) ws[i] = w[i];
    for (int i = tid; i < HID; i += 256) bs[i] = bias[i];
    __syncthreads();

    for (int pp = tid; pp < 7 * GG; pp += 256) {
        int lr = pp / GG, lc = pp % GG;
        int gr = r0 + lr;
        if (gr >= GG) continue;
        float patch[18];
#pragma unroll
        for (int ci = 0; ci < CC; ci++)
#pragma unroll
            for (int k = 0; k < 9; k++)
                patch[ci * 9 + k] = tile[ci * 9 * 51 + (lr + k / 3) * 51 + (lc + k % 3)];
        size_t obase = ((size_t)b * NPIX + gr * GG + lc) * 160;
        for (int co = 0; co < HID; co += 2) {
            uint32_t hpair = 0, lpair = 0;
#pragma unroll
            for (int q = 0; q < 2; q++) {
                float a = bs[co + q];
                const float2* wp = (const float2*)&ws[(co + q) * 18];
#pragma unroll
                for (int j = 0; j < 9; j++) {
                    float2 w2 = wp[j];
                    a = fmaf(patch[2 * j], w2.x, a);
                    a = fmaf(patch[2 * j + 1], w2.y, a);
                }
                a = fmaxf(a, 0.f);
                __nv_bfloat16 hx = __float2bfloat16(a);
                float lo = a - __bfloat162float(hx);
                __nv_bfloat16 lx = __float2bfloat16(lo);
                hpair |= (uint32_t)__bfloat16_as_ushort(hx) << (16 * q);
                lpair |= (uint32_t)__bfloat16_as_ushort(lx) << (16 * q);
            }
            *(uint32_t*)&g_h1h[obase + co] = hpair;
            *(uint32_t*)&g_h1l[obase + co] = lpair;
        }
    }
}

// ---------------- conv2: mma.sync bf16 3-term, 3-stage cp.async ring, ldmatrix ----------------
// smem: A[3buf][2pl][128x64B]=48KB at 0, B[3buf][2pl][160x64B]=60KB at 49152. 108KB.
#define C2_SMEM 110592

__global__ void __launch_bounds__(256, 2) conv2_mma_kernel(const float* __restrict__ bias) {
    extern __shared__ char smc[];
    uint32_t sb = smem_u32(smc);
    int tid = threadIdx.x;
    int lane = tid & 31, wid = tid >> 5;
    int b = blockIdx.y;
    int p0 = blockIdx.x * 128;
    int m0 = (wid & 3) * 32;
    int wn = wid >> 2;
    int n0 = wn * 80;

    int mrow = tid & 127;
    int aplane = tid >> 7;
    int pa = p0 + mrow; if (pa > NPIX - 1) pa = NPIX - 1;
    int par = pa / GG, pac = pa % GG;
    const __nv_bfloat16* abase = (aplane ? g_h1l : g_h1h) + (size_t)b * NPIX * 160;
    uint32_t adst0 = sb + aplane * 8192 + mrow * 64;
    int aswz = (mrow >> 1) & 3;

    int mat = lane >> 3, wl = lane & 7;
    int rowA0 = m0 + ((mat & 1) << 3) + wl;
    int rowA1 = rowA0 + 16;
    int sA0 = (rowA0 >> 1) & 3;
    int sA1 = (rowA1 >> 1) & 3;
    int kmatA = mat >> 1;
    int rowBb = n0 + (((mat >> 1) & 1) << 3) + wl;
    int kmatB = mat & 1;

    float acc[2][10][4];
#pragma unroll
    for (int mi = 0; mi < 2; mi++)
#pragma unroll
        for (int ni = 0; ni < 10; ni++)
#pragma unroll
            for (int j = 0; j < 4; j++) acc[mi][ni][j] = 0.f;

    auto load_stage = [&](int s, int bs) {
        int t = s / 5;
        int cb = (s - t * 5) * 32;
        int dr = t / 3 - 1, dc = t - (t / 3) * 3 - 1;
        int rr = par + dr, cc = pac + dc;
        bool val = ((unsigned)rr < GG) && ((unsigned)cc < GG);
        const __nv_bfloat16* src = abase + (size_t)(val ? (rr * GG + cc) : 0) * 160 + cb;
        int sz = val ? 16 : 0;
        uint32_t d = adst0 + bs * 16384;
#pragma unroll
        for (int j = 0; j < 4; j++)
            cp16(d + (((unsigned)(j ^ aswz)) << 4), (const char*)src + j * 16, sz);
        for (int rp = tid; rp < 320; rp += 256) {
            int bp = rp >= 160 ? 1 : 0;
            int n = rp - bp * 160;
            const __nv_bfloat16* wsrc = (bp ? g_wl : g_wh) + (size_t)(t * 160 + n) * 160 + cb;
            uint32_t bd = sb + 49152 + bs * 20480 + bp * 10240 + n * 64;
            int bsw = (n >> 1) & 3;
#pragma unroll
            for (int j = 0; j < 4; j++)
                cp16(bd + (((unsigned)(j ^ bsw)) << 4), (const char*)wsrc + j * 16, 16);
        }
        asm volatile("cp.async.commit_group;" ::: "memory");
    };

    load_stage(0, 0);
    load_stage(1, 1);
    for (int s = 0; s < 45; s++) {
        int bs = s % 3;
        if (s + 1 < 45) asm volatile("cp.async.wait_group 1;" ::: "memory");
        else            asm volatile("cp.async.wait_group 0;" ::: "memory");
        __syncthreads();
        uint32_t Ah = sb + bs * 16384;
        uint32_t Al = Ah + 8192;
        uint32_t Bh = sb + 49152 + bs * 20480;
        uint32_t Bl = Bh + 10240;
#pragma unroll
        for (int k16 = 0; k16 < 2; k16++) {
            int kc = k16 * 2;
            uint32_t ah[2][4], al[2][4];
            uint32_t offA0 = rowA0 * 64 + ((unsigned)((kc + kmatA) ^ sA0) << 4);
            uint32_t offA1 = rowA1 * 64 + ((unsigned)((kc + kmatA) ^ sA1) << 4);
            ldm4(ah[0][0], ah[0][1], ah[0][2], ah[0][3], Ah + offA0);
            ldm4(ah[1][0], ah[1][1], ah[1][2], ah[1][3], Ah + offA1);
            ldm4(al[0][0], al[0][1], al[0][2], al[0][3], Al + offA0);
            ldm4(al[1][0], al[1][1], al[1][2], al[1][3], Al + offA1);
#pragma unroll
            for (int np = 0; np < 5; np++) {
                int rowB = rowBb + np * 16;
                uint32_t offB = rowB * 64 + ((unsigned)((kc + kmatB) ^ ((rowB >> 1) & 3)) << 4);
                uint32_t bh[4], bl[4];
                ldm4(bh[0], bh[1], bh[2], bh[3], Bh + offB);
                ldm4(bl[0], bl[1], bl[2], bl[3], Bl + offB);
#pragma unroll
                for (int sub = 0; sub < 2; sub++) {
                    int ni = np * 2 + sub;
                    uint32_t h0 = bh[sub * 2], h1 = bh[sub * 2 + 1];
                    uint32_t l0 = bl[sub * 2], l1 = bl[sub * 2 + 1];
#pragma unroll
                    for (int mi = 0; mi < 2; mi++) {
                        mma16816(acc[mi][ni], ah[mi][0], ah[mi][1], ah[mi][2], ah[mi][3], h0, h1);
                        mma16816(acc[mi][ni], ah[mi][0], ah[mi][1], ah[mi][2], ah[mi][3], l0, l1);
                        mma16816(acc[mi][ni], al[mi][0], al[mi][1], al[mi][2], al[mi][3], h0, h1);
                    }
                }
            }
        }
        if (s + 2 < 45) load_stage(s + 2, (s + 2) % 3);
    }
    __syncthreads();

    // epilogue: stage through smem; bias+relu; split to bf16 hi/lo channel-last planes
    float* DT = (float*)smc;
    int crow = lane >> 2;
#pragma unroll 1
    for (int h = 0; h < 2; h++) {
        if (wn == h) {
#pragma unroll
            for (int mi = 0; mi < 2; mi++)
#pragma unroll
                for (int ni = 0; ni < 10; ni++) {
                    int mb = m0 + mi * 16 + crow;
                    int nb = ni * 8 + (lane & 3) * 2;
                    DT[mb * 80 + nb]           = acc[mi][ni][0];
                    DT[mb * 80 + nb + 1]       = acc[mi][ni][1];
                    DT[(mb + 8) * 80 + nb]     = acc[mi][ni][2];
                    DT[(mb + 8) * 80 + nb + 1] = acc[mi][ni][3];
                }
        }
        __syncthreads();
        for (int idx = tid; idx < 1280; idx += 256) {
            int m = idx / 10, j = idx % 10;
            int p = p0 + m;
            if (p >= NPIX) continue;
            uint32_t hw[4], lw[4];
#pragma unroll
            for (int e2 = 0; e2 < 4; e2++) {
                uint32_t hpair = 0, lpair = 0;
#pragma unroll
                for (int q = 0; q < 2; q++) {
                    int co = h * 80 + j * 8 + e2 * 2 + q;
                    float v = 0.f;
                    if (co < HID) v = fmaxf(DT[m * 80 + j * 8 + e2 * 2 + q] + __ldg(&bias[co]), 0.f);
                    __nv_bfloat16 hx = __float2bfloat16(v);
                    float lo = v - __bfloat162float(hx);
                    __nv_bfloat16 lx = __float2bfloat16(lo);
                    hpair |= (uint32_t)__bfloat16_as_ushort(hx) << (16 * q);
                    lpair |= (uint32_t)__bfloat16_as_ushort(lx) << (16 * q);
                }
                hw[e2] = hpair;
                lw[e2] = lpair;
            }
            size_t off = ((size_t)b * NPIX + p) * 160 + h * 80 + j * 8;
            *(uint4*)&g_h2h[off] = make_uint4(hw[0], hw[1], hw[2], hw[3]);
            *(uint4*)&g_h2l[off] = make_uint4(lw[0], lw[1], lw[2], lw[3]);
        }
        __syncthreads();
    }
}

// ---------------- trans: same pipeline, N=80, pad=2, fused softmax epilogue ----------------
// smem: A[3buf][2pl][128x64B]=48KB at 0, B[3buf][2pl][80x64B]=30KB at 49152. 78KB.
#define TR_SMEM 79872

__global__ void __launch_bounds__(256, 2) trans_mma_kernel() {
    extern __shared__ char smc[];
    uint32_t sb = smem_u32(smc);
    int tid = threadIdx.x;
    int lane = tid & 31, wid = tid >> 5;
    int b = blockIdx.y;
    int p0 = blockIdx.x * 128;
    int m0 = (wid & 3) * 32;
    int wn = wid >> 2;
    int n0 = wn * 40;

    int mrow = tid & 127;
    int aplane = tid >> 7;
    int pa = p0 + mrow;
    bool pvalid = pa < NPT;
    int pc = pvalid ? pa : NPT - 1;
    int par = pc / HP, pac = pc % HP;
    const __nv_bfloat16* abase = (aplane ? g_h2l : g_h2h) + (size_t)b * NPIX * 160;
    uint32_t adst0 = sb + aplane * 8192 + mrow * 64;
    int aswz = (mrow >> 1) & 3;

    int mat = lane >> 3, wl = lane & 7;
    int rowA0 = m0 + ((mat & 1) << 3) + wl;
    int rowA1 = rowA0 + 16;
    int sA0 = (rowA0 >> 1) & 3;
    int sA1 = (rowA1 >> 1) & 3;
    int kmatA = mat >> 1;
    int rowBb = n0 + (((mat >> 1) & 1) << 3) + wl;
    int kmatB = mat & 1;
    int rowT = n0 + 32 + wl;
    int kmatT = (lane >> 3) & 1;
    int sT = (rowT >> 1) & 3;

    float acc[2][5][4];
#pragma unroll
    for (int mi = 0; mi < 2; mi++)
#pragma unroll
        for (int ni = 0; ni < 5; ni++)
#pragma unroll
            for (int j = 0; j < 4; j++) acc[mi][ni][j] = 0.f;

    auto load_stage = [&](int s, int bs) {
        int t = s / 5;
        int cb = (s - t * 5) * 32;
        int dr = t / 3 - 2, dc = t - (t / 3) * 3 - 2;
        int rr = par + dr, cc = pac + dc;
        bool val = pvalid && ((unsigned)rr < GG) && ((unsigned)cc < GG);
        const __nv_bfloat16* src = abase + (size_t)(val ? (rr * GG + cc) : 0) * 160 + cb;
        int sz = val ? 16 : 0;
        uint32_t d = adst0 + bs * 16384;
#pragma unroll
        for (int j = 0; j < 4; j++)
            cp16(d + (((unsigned)(j ^ aswz)) << 4), (const char*)src + j * 16, sz);
        if (tid < 160) {
            int bp = tid >= 80 ? 1 : 0;
            int n = tid - bp * 80;
            const __nv_bfloat16* wsrc = (bp ? g_twl : g_twh) + (size_t)(t * 80 + n) * 160 + cb;
            uint32_t bd = sb + 49152 + bs * 10240 + bp * 5120 + n * 64;
            int bsw = (n >> 1) & 3;
#pragma unroll
            for (int j = 0; j < 4; j++)
                cp16(bd + (((unsigned)(j ^ bsw)) << 4), (const char*)wsrc + j * 16, 16);
        }
        asm volatile("cp.async.commit_group;" ::: "memory");
    };

    load_stage(0, 0);
    load_stage(1, 1);
    for (int s = 0; s < 45; s++) {
        int bs = s % 3;
        if (s + 1 < 45) asm volatile("cp.async.wait_group 1;" ::: "memory");
        else            asm volatile("cp.async.wait_group 0;" ::: "memory");
        __syncthreads();
        uint32_t Ah = sb + bs * 16384;
        uint32_t Al = Ah + 8192;
        uint32_t Bh = sb + 49152 + bs * 10240;
        uint32_t Bl = Bh + 5120;
#pragma unroll
        for (int k16 = 0; k16 < 2; k16++) {
            int kc = k16 * 2;
            uint32_t ah[2][4], al[2][4];
            uint32_t offA0 = rowA0 * 64 + ((unsigned)((kc + kmatA) ^ sA0) << 4);
            uint32_t offA1 = rowA1 * 64 + ((unsigned)((kc + kmatA) ^ sA1) << 4);
            ldm4(ah[0][0], ah[0][1], ah[0][2], ah[0][3], Ah + offA0);
            ldm4(ah[1][0], ah[1][1], ah[1][2], ah[1][3], Ah + offA1);
            ldm4(al[0][0], al[0][1], al[0][2], al[0][3], Al + offA0);
            ldm4(al[1][0], al[1][1], al[1][2], al[1][3], Al + offA1);
#pragma unroll
            for (int np = 0; np < 2; np++) {
                int rowB = rowBb + np * 16;
                uint32_t offB = rowB * 64 + ((unsigned)((kc + kmatB) ^ ((rowB >> 1) & 3)) << 4);
                uint32_t bh[4], bl[4];
                ldm4(bh[0], bh[1], bh[2], bh[3], Bh + offB);
                ldm4(bl[0], bl[1], bl[2], bl[3], Bl + offB);
#pragma unroll
                for (int sub = 0; sub < 2; sub++) {
                    int ni = np * 2 + sub;
                    uint32_t h0 = bh[sub * 2], h1 = bh[sub * 2 + 1];
                    uint32_t l0 = bl[sub * 2], l1 = bl[sub * 2 + 1];
#pragma unroll
                    for (int mi = 0; mi < 2; mi++) {
                        mma16816(acc[mi][ni], ah[mi][0], ah[mi][1], ah[mi][2], ah[mi][3], h0, h1);
                        mma16816(acc[mi][ni], ah[mi][0], ah[mi][1], ah[mi][2], ah[mi][3], l0, l1);
                        mma16816(acc[mi][ni], al[mi][0], al[mi][1], al[mi][2], al[mi][3], h0, h1);
                    }
                }
            }
            {
                uint32_t offT = rowT * 64 + ((unsigned)((kc + kmatT) ^ sT) << 4);
                uint32_t th0, th1, tl0, tl1;
                ldm2(th0, th1, Bh + offT);
                ldm2(tl0, tl1, Bl + offT);
#pragma unroll
                for (int mi = 0; mi < 2; mi++) {
                    mma16816(acc[mi][4], ah[mi][0], ah[mi][1], ah[mi][2], ah[mi][3], th0, th1);
                    mma16816(acc[mi][4], ah[mi][0], ah[mi][1], ah[mi][2], ah[mi][3], tl0, tl1);
                    mma16816(acc[mi][4], al[mi][0], al[mi][1], al[mi][2], al[mi][3], th0, th1);
                }
            }
        }
        if (s + 2 < 45) load_stage(s + 2, (s + 2) % 3);
    }
    __syncthreads();

    // epilogue: stage D[128 x 80], per-pixel softmax over 8 groups of 9 + reward
    float* DT = (float*)smc;
    int crow = lane >> 2;
#pragma unroll
    for (int mi = 0; mi < 2; mi++)
#pragma unroll
        for (int ni = 0; ni < 5; ni++) {
            int mb = m0 + mi * 16 + crow;
            int nb = n0 + ni * 8 + (lane & 3) * 2;
            DT[mb * 80 + nb]           = acc[mi][ni][0];
            DT[mb * 80 + nb + 1]       = acc[mi][ni][1];
            DT[(mb + 8) * 80 + nb]     = acc[mi][ni][2];
            DT[(mb + 8) * 80 + nb + 1] = acc[mi][ni][3];
        }
    __syncthreads();
    if (tid < 128) {
        int p = p0 + tid;
        if (p < NPT) {
            const float* row = &DT[tid * 80];
#pragma unroll
            for (int a = 0; a < AA; a++) {
                float av[9];
#pragma unroll
                for (int k = 0; k < 9; k++) av[k] = row[a * 9 + k];
                float m = av[0];
#pragma unroll
                for (int k = 1; k < 9; k++) m = fmaxf(m, av[k]);
                float e[9];
                float sum = 0.f;
#pragma unroll
                for (int k = 0; k < 9; k++) { e[k] = expf(av[k] - m); sum += e[k]; }
                float inv = 1.0f / sum;
#pragma unroll
                for (int k = 0; k < 9; k++)
                    g_sT[((b * AA + a) * 9 + k) * NPT + p] = e[k] * inv;
            }
            g_reward[b * NPT + p] = row[72];
        }
    }
}

// ---------------- VI loop (unchanged) ----------------
__global__ __launch_bounds__(1024) void vi_kernel() {
    int b = blockIdx.x;
    __shared__ float vpad[53 * 53];
    __shared__ float rsh[NPT];
    int tid = threadIdx.x;
    for (int i = tid; i < 53 * 53; i += 1024) vpad[i] = 0.f;
    for (int i = tid; i < NPT; i += 1024) rsh[i] = g_reward[b * NPT + i];
    const float* __restrict__ sb = &g_sT[(size_t)b * AA * 9 * NPT];

    for (int it = 0; it < KK; it++) {
        __syncthreads();
        float vnew[3];
#pragma unroll
        for (int j = 0; j < 3; j++) {
            int p = tid + j * 1024;
            if (p < NPT) {
                int r = p / HP, c = p % HP;
                float patch[9];
#pragma unroll
                for (int k = 0; k < 9; k++)
                    patch[k] = vpad[(r + k / 3) * 53 + (c + k % 3)];
                float rwv = rsh[p];
                float vm = -3.4e38f;
#pragma unroll
                for (int a = 0; a < AA; a++) {
                    float q = rwv;
#pragma unroll
                    for (int k = 0; k < 9; k++)
                        q = fmaf(sb[(a * 9 + k) * NPT + p], patch[k], q);
                    vm = fmaxf(vm, q);
                    if (it == KK - 1 && r < GG && c < GG)
                        g_qc[((b * AA + a) * GG + r) * GG + c] = q;
                }
                vnew[j] = vm;
            }
        }
        __syncthreads();
#pragma unroll
        for (int j = 0; j < 3; j++) {
            int p = tid + j * 1024;
            if (p < NPT) {
                int r = p / HP, c = p % HP;
                vpad[(r + 1) * 53 + (c + 1)] = vnew[j];
            }
        }
    }
}

// ---------------- head (unchanged) ----------------
__global__ __launch_bounds__(256) void head_kernel(const float* __restrict__ w1,
                                                   const float* __restrict__ b1g,
                                                   const float* __restrict__ w2,
                                                   const float* __restrict__ b2g,
                                                   float* __restrict__ out) {
    int b = blockIdx.y;
    int p = blockIdx.x * 256 + threadIdx.x;
    __shared__ float w1s[HID * AA];
    __shared__ float b1s[HID];
    __shared__ float w2s[HID * AA];
    __shared__ float b2s[AA];
    int tid = threadIdx.x;
    for (int i = tid; i < HID * AA; i += 256) w1s[i] = w1[i];
    for (int i = tid; i < HID; i += 256) b1s[i] = b1g[i];
    for (int i = tid; i < HID * AA; i += 256) {
        int a = i / HID, c = i % HID;
        w2s[c * AA + a] = w2[i];
    }
    for (int i = tid; i < AA; i += 256) b2s[i] = b2g[i];
    __syncthreads();
    if (p >= NPIX) return;

    float qv[AA];
#pragma unroll
    for (int a = 0; a < AA; a++) qv[a] = g_qc[(b * AA + a) * NPIX + p];
    float o[AA];
#pragma unroll
    for (int a = 0; a < AA; a++) o[a] = b2s[a];

    for (int c = 0; c < HID; c++) {
        const float2* wp1 = (const float2*)&w1s[c * 8];
        float m = b1s[c];
#pragma unroll
        for (int j = 0; j < 4; j++) {
            float2 ww = wp1[j];
            m = fmaf(qv[2 * j], ww.x, m);
            m = fmaf(qv[2 * j + 1], ww.y, m);
        }
        m = fmaxf(m, 0.f);
        const float2* wp2 = (const float2*)&w2s[c * 8];
#pragma unroll
        for (int j = 0; j < 4; j++) {
            float2 ww = wp2[j];
            o[2 * j]     = fmaf(m, ww.x, o[2 * j]);
            o[2 * j + 1] = fmaf(m, ww.y, o[2 * j + 1]);
        }
    }
#pragma unroll
    for (int a = 0; a < AA; a++)
        out[(b * AA + a) * NPIX + p] = o[a];
}

// ---------------- launch ----------------
extern "C" void kernel_launch(void* const* d_in, const int* in_sizes, int n_in,
                              void* d_out, int out_size) {
    const float* grid_in = (const float*)d_in[0];
    const float* h1_w = (const float*)d_in[3];
    const float* h1_b = (const float*)d_in[4];
    const float* h2_w = (const float*)d_in[5];
    const float* h2_b = (const float*)d_in[6];
    const float* r_w  = (const float*)d_in[7];
    const float* t_w  = (const float*)d_in[8];
    const float* a1_w = (const float*)d_in[9];
    const float* a1_b = (const float*)d_in[10];
    const float* a2_w = (const float*)d_in[11];
    const float* a2_b = (const float*)d_in[12];

    cudaFuncSetAttribute(conv2_mma_kernel, cudaFuncAttributeMaxDynamicSharedMemorySize, C2_SMEM);
    cudaFuncSetAttribute(trans_mma_kernel, cudaFuncAttributeMaxDynamicSharedMemorySize, TR_SMEM);

    wsplit_kernel<<<(9 * 160 * 160 + 255) / 256, 256>>>(h2_w);
    wsplit2_kernel<<<(9 * 80 * 160 + 255) / 256, 256>>>(t_w, r_w);
    conv1_kernel<<<dim3(7, BB), 256>>>(grid_in, h1_w, h1_b);
    conv2_mma_kernel<<<dim3((NPIX + 127) / 128, BB), 256, C2_SMEM>>>(h2_b);
    trans_mma_kernel<<<dim3((NPT + 127) / 128, BB), 256, TR_SMEM>>>();
    vi_kernel<<<BB, 1024>>>();
    head_kernel<<<dim3(10, BB), 256>>>(a1_w, a1_b, a2_w, a2_b, (float*)d_out);
}